// round 3
// baseline (speedup 1.0000x reference)
#include <cuda_runtime.h>
#include <cstdint>

#define PB 4
#define PC 2048
#define PE 1024
#define PH 16
#define PHD 64
#define PM (PB*PC)        // 8192
#define PK PE             // 1024
#define PN3 (3*PE)        // 3072

// tf32 bit-pattern scratch buffers (device globals: allocation-free rule)
__device__ uint32_t g_xt [(size_t)PM*PK];
__device__ uint32_t g_wat[(size_t)PK*PN3];
__device__ uint32_t g_wpt[(size_t)PK*PE];
__device__ uint32_t g_qt [(size_t)PB*PH*PC*PHD];
__device__ uint32_t g_kt [(size_t)PB*PH*PC*PHD];
__device__ uint32_t g_vt [(size_t)PB*PH*PC*PHD];
__device__ uint32_t g_yt [(size_t)PM*PE];

// ---------------------------------------------------------------------------
// Helpers
// ---------------------------------------------------------------------------
__device__ __forceinline__ uint32_t f2t(float x) {
    uint32_t r;
    asm("cvt.rna.tf32.f32 %0, %1;" : "=r"(r) : "f"(x));
    return r;
}
__device__ __forceinline__ float ex2(float x) {
    float r;
    asm("ex2.approx.f32 %0, %1;" : "=f"(r) : "f"(x));
    return r;
}
__device__ __forceinline__ void mma_tf32(float* c, const uint32_t* a, const uint32_t* b) {
    asm volatile(
        "mma.sync.aligned.m16n8k8.row.col.f32.tf32.tf32.f32 "
        "{%0,%1,%2,%3}, {%4,%5,%6,%7}, {%8,%9}, {%0,%1,%2,%3};"
        : "+f"(c[0]), "+f"(c[1]), "+f"(c[2]), "+f"(c[3])
        : "r"(a[0]), "r"(a[1]), "r"(a[2]), "r"(a[3]), "r"(b[0]), "r"(b[1]));
}
__device__ __forceinline__ void cp16(void* smem_dst, const void* gsrc) {
    uint32_t d = (uint32_t)__cvta_generic_to_shared(smem_dst);
    asm volatile("cp.async.cg.shared.global [%0], [%1], 16;" :: "r"(d), "l"(gsrc));
}
__device__ __forceinline__ void cp_commit() { asm volatile("cp.async.commit_group;"); }
template<int N> __device__ __forceinline__ void cp_wait() {
    asm volatile("cp.async.wait_group %0;" :: "n"(N));
}

// ---------------------------------------------------------------------------
// fp32 -> tf32 bit-pattern conversion (pre-pass)
// ---------------------------------------------------------------------------
__global__ void cvt4_kernel(const float4* __restrict__ src, uint4* __restrict__ dst, int n4)
{
    int i = blockIdx.x * blockDim.x + threadIdx.x;
    if (i < n4) {
        float4 v = src[i];
        uint4 o;
        o.x = f2t(v.x); o.y = f2t(v.y); o.z = f2t(v.z); o.w = f2t(v.w);
        dst[i] = o;
    }
}

// ---------------------------------------------------------------------------
// TF32 GEMM v2: CTA 256x128, BK=32, 8 warps (4m x 2n), warp tile 64x64
// As [m][k] pitch 36 (4 mod 32), Bs [k][n] pitch 136 (8 mod 32): conflict-free
// EPI 0: A=g_xt, B=g_wat, scatter head-major tf32 q/k/v
// EPI 1: A=g_yt, B=g_wpt, plain fp32 C
// ---------------------------------------------------------------------------
#define GAP 36
#define GBP 136
#define GASZ (256*GAP)
#define GBSZ (32*GBP)

template<int N, int EPI>
__global__ __launch_bounds__(256, 1)
void gemm2(float* __restrict__ Cout)
{
    extern __shared__ uint32_t sm[];
    uint32_t* As = sm;                // 2 * GASZ
    uint32_t* Bs = sm + 2 * GASZ;     // 2 * GBSZ

    const uint32_t* Ap = EPI ? g_yt  : g_xt;
    const uint32_t* Bp = EPI ? g_wpt : g_wat;
    const int K = PK;

    const int tid = threadIdx.x;
    const int warp = tid >> 5, lane = tid & 31;
    const int l4 = lane >> 2, lq = lane & 3;
    const int wm = (warp & 3) * 64, wn = (warp >> 2) * 64;
    const int bx = blockIdx.x, by = blockIdx.y;

    float acc[4][8][4];
    #pragma unroll
    for (int i = 0; i < 4; i++)
        #pragma unroll
        for (int j = 0; j < 8; j++)
            #pragma unroll
            for (int r = 0; r < 4; r++) acc[i][j][r] = 0.f;

    auto issue = [&](int it) {
        int buf = it & 1;
        int k0 = it * 32;
        uint32_t* Ab = As + buf * GASZ;
        uint32_t* Bb = Bs + buf * GBSZ;
        #pragma unroll
        for (int i = 0; i < 8; i++) {
            int idx = tid + i * 256;
            int r = idx >> 3, c4 = (idx & 7) * 4;
            cp16(Ab + r * GAP + c4, Ap + (size_t)(by * 256 + r) * K + k0 + c4);
        }
        #pragma unroll
        for (int i = 0; i < 4; i++) {
            int idx = tid + i * 256;
            int kr = idx >> 5, c4 = (idx & 31) * 4;
            cp16(Bb + kr * GBP + c4, Bp + (size_t)(k0 + kr) * N + bx * 128 + c4);
        }
        cp_commit();
    };

    issue(0);
    const int NIT = K / 32;
    #pragma unroll 1
    for (int it = 0; it < NIT; ++it) {
        if (it + 1 < NIT) { issue(it + 1); cp_wait<1>(); }
        else              { cp_wait<0>(); }
        __syncthreads();
        const uint32_t* Ab = As + (it & 1) * GASZ;
        const uint32_t* Bb = Bs + (it & 1) * GBSZ;

        #pragma unroll
        for (int ks = 0; ks < 4; ks++) {
            int k = ks * 8;
            uint32_t a[4][4], b[8][2];
            #pragma unroll
            for (int mt = 0; mt < 4; mt++) {
                int m = wm + mt * 16 + l4;
                a[mt][0] = Ab[m * GAP + k + lq];
                a[mt][1] = Ab[(m + 8) * GAP + k + lq];
                a[mt][2] = Ab[m * GAP + k + 4 + lq];
                a[mt][3] = Ab[(m + 8) * GAP + k + 4 + lq];
            }
            #pragma unroll
            for (int nt = 0; nt < 8; nt++) {
                int n = wn + nt * 8 + l4;
                b[nt][0] = Bb[(k + lq) * GBP + n];
                b[nt][1] = Bb[(k + 4 + lq) * GBP + n];
            }
            #pragma unroll
            for (int mt = 0; mt < 4; mt++)
                #pragma unroll
                for (int nt = 0; nt < 8; nt++)
                    mma_tf32(acc[mt][nt], a[mt], b[nt]);
        }
        __syncthreads();
    }

    // Epilogue
    #pragma unroll
    for (int mt = 0; mt < 4; mt++) {
        #pragma unroll
        for (int nt = 0; nt < 8; nt++) {
            int gm = by * 256 + wm + mt * 16 + l4;
            int gn = bx * 128 + wn + nt * 8 + lq * 2;
            if (EPI == 0) {
                int which = gn >> 10;
                int hn = gn & 1023;
                int h = hn >> 6, d = hn & 63;
                uint32_t* dst = (which == 0) ? g_qt : (which == 1 ? g_kt : g_vt);
                int b_ = gm >> 11, c_ = gm & 2047;
                size_t base = (((size_t)(b_ * PH + h)) * PC + c_) * PHD + d;
                uint2 u0 = make_uint2(f2t(acc[mt][nt][0]), f2t(acc[mt][nt][1]));
                uint2 u1 = make_uint2(f2t(acc[mt][nt][2]), f2t(acc[mt][nt][3]));
                *(uint2*)&dst[base] = u0;
                *(uint2*)&dst[base + (size_t)8 * PHD] = u1;
            } else {
                *(float2*)&Cout[(size_t)gm * N + gn] =
                    make_float2(acc[mt][nt][0], acc[mt][nt][1]);
                *(float2*)&Cout[(size_t)(gm + 8) * N + gn] =
                    make_float2(acc[mt][nt][2], acc[mt][nt][3]);
            }
        }
    }
}

// ---------------------------------------------------------------------------
// Flash attention v3: CTA = 128 q-rows x (b*h). 8 warps (16 rows each).
// Q fragments persistent in registers (tf32 from g_qt). K/V tf32 via cp.async.
// Softmax in log2 domain; P C->A layout via quad shuffles.
// ---------------------------------------------------------------------------
#define KP 68
#define VP 72
#define KS_SZ (64*KP)
#define VS_SZ (64*VP)

__global__ __launch_bounds__(256, 2)
void attn3()
{
    extern __shared__ uint32_t sm[];
    uint32_t* Ks = sm;                // 2 * KS_SZ
    uint32_t* Vs = sm + 2 * KS_SZ;    // 2 * VS_SZ

    const int qb = (int)gridDim.x - 1 - (int)blockIdx.x;   // big work first
    const int bh = blockIdx.y;
    const uint32_t* Qg = g_qt + (size_t)bh * PC * PHD + (size_t)qb * 128 * PHD;
    const uint32_t* Kg = g_kt + (size_t)bh * PC * PHD;
    const uint32_t* Vg = g_vt + (size_t)bh * PC * PHD;

    const int tid = threadIdx.x;
    const int warp = tid >> 5, lane = tid & 31;
    const int l4 = lane >> 2, lq = lane & 3;
    const int mrow = warp * 16;

    // Persistent Q fragments (already tf32 in gmem)
    uint32_t aq[8][4];
    {
        const int r0 = mrow + l4, r1 = r0 + 8;
        #pragma unroll
        for (int kt = 0; kt < 8; kt++) {
            int k = kt * 8;
            aq[kt][0] = Qg[r0 * PHD + k + lq];
            aq[kt][1] = Qg[r1 * PHD + k + lq];
            aq[kt][2] = Qg[r0 * PHD + k + 4 + lq];
            aq[kt][3] = Qg[r1 * PHD + k + 4 + lq];
        }
    }

    auto issueKV = [&](int jb) {
        int buf = jb & 1;
        uint32_t* Kb = Ks + buf * KS_SZ;
        uint32_t* Vb = Vs + buf * VS_SZ;
        const uint32_t* kg = Kg + (size_t)jb * 64 * PHD;
        const uint32_t* vg = Vg + (size_t)jb * 64 * PHD;
        #pragma unroll
        for (int i = 0; i < 4; i++) {
            int idx = tid + i * 256;
            int r = idx >> 4, c4 = (idx & 15) * 4;
            cp16(Kb + r * KP + c4, kg + r * PHD + c4);
            cp16(Vb + r * VP + c4, vg + r * PHD + c4);
        }
        cp_commit();
    };

    float o[8][4];
    #pragma unroll
    for (int nt = 0; nt < 8; nt++)
        #pragma unroll
        for (int j = 0; j < 4; j++) o[nt][j] = 0.f;
    float mx0 = -1e30f, mx1 = -1e30f, ls0 = 0.f, ls1 = 0.f;

    const float SC = 0.125f * 1.4426950408889634f;   // 1/sqrt(64) * log2(e)
    const int NJB = 2 * qb + 2;
    const int r0g = qb * 128 + mrow + l4;
    const int r1g = r0g + 8;

    issueKV(0);

    #pragma unroll 1
    for (int jb = 0; jb < NJB; ++jb) {
        if (jb + 1 < NJB) { issueKV(jb + 1); cp_wait<1>(); }
        else              { cp_wait<0>(); }
        __syncthreads();
        const uint32_t* Kb = Ks + (jb & 1) * KS_SZ;
        const uint32_t* Vb = Vs + (jb & 1) * VS_SZ;

        // S = Q K^T
        float s[8][4];
        #pragma unroll
        for (int nt = 0; nt < 8; nt++)
            #pragma unroll
            for (int j = 0; j < 4; j++) s[nt][j] = 0.f;

        #pragma unroll
        for (int kt = 0; kt < 8; kt++) {
            int k = kt * 8;
            #pragma unroll
            for (int nt = 0; nt < 8; nt++) {
                uint32_t b[2];
                b[0] = Kb[(nt * 8 + l4) * KP + k + lq];
                b[1] = Kb[(nt * 8 + l4) * KP + k + 4 + lq];
                mma_tf32(s[nt], aq[kt], b);
            }
        }

        // scale (log2 domain) + causal mask
        #pragma unroll
        for (int nt = 0; nt < 8; nt++)
            #pragma unroll
            for (int j = 0; j < 4; j++) s[nt][j] *= SC;

        if (jb * 64 + 63 > qb * 128 + mrow) {
            #pragma unroll
            for (int nt = 0; nt < 8; nt++) {
                int cn = jb * 64 + nt * 8 + lq * 2;
                if (cn     > r0g) s[nt][0] = -1e30f;
                if (cn + 1 > r0g) s[nt][1] = -1e30f;
                if (cn     > r1g) s[nt][2] = -1e30f;
                if (cn + 1 > r1g) s[nt][3] = -1e30f;
            }
        }

        // online softmax
        float rm0 = -1e30f, rm1 = -1e30f;
        #pragma unroll
        for (int nt = 0; nt < 8; nt++) {
            rm0 = fmaxf(rm0, fmaxf(s[nt][0], s[nt][1]));
            rm1 = fmaxf(rm1, fmaxf(s[nt][2], s[nt][3]));
        }
        rm0 = fmaxf(rm0, __shfl_xor_sync(0xffffffffu, rm0, 1));
        rm0 = fmaxf(rm0, __shfl_xor_sync(0xffffffffu, rm0, 2));
        rm1 = fmaxf(rm1, __shfl_xor_sync(0xffffffffu, rm1, 1));
        rm1 = fmaxf(rm1, __shfl_xor_sync(0xffffffffu, rm1, 2));
        float nm0 = fmaxf(mx0, rm0), nm1 = fmaxf(mx1, rm1);
        float al0 = ex2(mx0 - nm0), al1 = ex2(mx1 - nm1);
        float rs0 = 0.f, rs1 = 0.f;
        #pragma unroll
        for (int nt = 0; nt < 8; nt++) {
            s[nt][0] = ex2(s[nt][0] - nm0); rs0 += s[nt][0];
            s[nt][1] = ex2(s[nt][1] - nm0); rs0 += s[nt][1];
            s[nt][2] = ex2(s[nt][2] - nm1); rs1 += s[nt][2];
            s[nt][3] = ex2(s[nt][3] - nm1); rs1 += s[nt][3];
        }
        rs0 += __shfl_xor_sync(0xffffffffu, rs0, 1);
        rs0 += __shfl_xor_sync(0xffffffffu, rs0, 2);
        rs1 += __shfl_xor_sync(0xffffffffu, rs1, 1);
        rs1 += __shfl_xor_sync(0xffffffffu, rs1, 2);
        ls0 = ls0 * al0 + rs0; mx0 = nm0;
        ls1 = ls1 * al1 + rs1; mx1 = nm1;
        #pragma unroll
        for (int nt = 0; nt < 8; nt++) {
            o[nt][0] *= al0; o[nt][1] *= al0;
            o[nt][2] *= al1; o[nt][3] *= al1;
        }

        // O += P @ V  (P C-layout -> A-layout via quad shuffles)
        #pragma unroll
        for (int kt = 0; kt < 8; kt++) {
            int src0 = (lane & ~3) | (lq >> 1);
            int src1 = src0 + 2;
            float v00 = __shfl_sync(0xffffffffu, s[kt][0], src0);
            float v01 = __shfl_sync(0xffffffffu, s[kt][1], src0);
            float v10 = __shfl_sync(0xffffffffu, s[kt][2], src0);
            float v11 = __shfl_sync(0xffffffffu, s[kt][3], src0);
            float w00 = __shfl_sync(0xffffffffu, s[kt][0], src1);
            float w01 = __shfl_sync(0xffffffffu, s[kt][1], src1);
            float w10 = __shfl_sync(0xffffffffu, s[kt][2], src1);
            float w11 = __shfl_sync(0xffffffffu, s[kt][3], src1);
            bool odd = (lq & 1);
            uint32_t a[4];
            a[0] = f2t(odd ? v01 : v00);
            a[1] = f2t(odd ? v11 : v10);
            a[2] = f2t(odd ? w01 : w00);
            a[3] = f2t(odd ? w11 : w10);
            int k = kt * 8;
            #pragma unroll
            for (int nt = 0; nt < 8; nt++) {
                uint32_t b[2];
                b[0] = Vb[(k + lq) * VP + nt * 8 + l4];
                b[1] = Vb[(k + 4 + lq) * VP + nt * 8 + l4];
                mma_tf32(o[nt], a, b);
            }
        }
        __syncthreads();
    }

    // Epilogue: write y (tf32) in [B,C,E], e = h*64 + d
    int h_ = bh & 15, b_ = bh >> 4;
    float il0 = 1.0f / ls0, il1 = 1.0f / ls1;
    #pragma unroll
    for (int nt = 0; nt < 8; nt++) {
        int d = nt * 8 + lq * 2;
        size_t base = ((size_t)b_ * PC + r0g) * PE + h_ * PHD + d;
        *(uint2*)&g_yt[base] =
            make_uint2(f2t(o[nt][0] * il0), f2t(o[nt][1] * il0));
        *(uint2*)&g_yt[base + (size_t)8 * PE] =
            make_uint2(f2t(o[nt][2] * il1), f2t(o[nt][3] * il1));
    }
}

// ---------------------------------------------------------------------------
extern "C" void kernel_launch(void* const* d_in, const int* in_sizes, int n_in,
                              void* d_out, int out_size)
{
    const float* x  = (const float*)d_in[0];
    const float* Wa = (const float*)d_in[1];
    const float* Wp = (const float*)d_in[2];
    float* out = (float*)d_out;

    size_t smemG = (size_t)(2 * GASZ + 2 * GBSZ) * sizeof(uint32_t);   // 108544
    size_t smemA = (size_t)(2 * KS_SZ + 2 * VS_SZ) * sizeof(uint32_t); // 71680

    cudaFuncSetAttribute(gemm2<PN3, 0>,
                         cudaFuncAttributeMaxDynamicSharedMemorySize, (int)smemG);
    cudaFuncSetAttribute(gemm2<PE, 1>,
                         cudaFuncAttributeMaxDynamicSharedMemorySize, (int)smemG);
    cudaFuncSetAttribute(attn3,
                         cudaFuncAttributeMaxDynamicSharedMemorySize, (int)smemA);

    // Pre-pass: fp32 -> tf32 bit patterns
    uint4* d_xt;  cudaGetSymbolAddress((void**)&d_xt,  g_xt);
    uint4* d_wat; cudaGetSymbolAddress((void**)&d_wat, g_wat);
    uint4* d_wpt; cudaGetSymbolAddress((void**)&d_wpt, g_wpt);
    {
        int n4 = PM * PK / 4;
        cvt4_kernel<<<(n4 + 255) / 256, 256>>>((const float4*)x, d_xt, n4);
        n4 = PK * PN3 / 4;
        cvt4_kernel<<<(n4 + 255) / 256, 256>>>((const float4*)Wa, d_wat, n4);
        n4 = PK * PE / 4;
        cvt4_kernel<<<(n4 + 255) / 256, 256>>>((const float4*)Wp, d_wpt, n4);
    }

    gemm2<PN3, 0><<<dim3(PN3 / 128, PM / 256), 256, smemG>>>(nullptr);
    attn3<<<dim3(PC / 128, PB * PH), 256, smemA>>>();
    gemm2<PE, 1><<<dim3(PE / 128, PM / 256), 256, smemG>>>(out);
}

// round 5
// speedup vs baseline: 1.0368x; 1.0368x over previous
#include <cuda_runtime.h>
#include <cstdint>

#define PB 4
#define PC 2048
#define PE 1024
#define PH 16
#define PHD 64
#define PM (PB*PC)        // 8192
#define PK PE             // 1024
#define PN3 (3*PE)        // 3072

// tf32 bit-pattern scratch (device globals: allocation-free rule)
__device__ uint32_t g_xt [(size_t)PM*PK];
__device__ uint32_t g_wat[(size_t)PK*PN3];
__device__ uint32_t g_wpt[(size_t)PK*PE];
__device__ uint32_t g_qt [(size_t)PB*PH*PC*PHD];
__device__ uint32_t g_kt [(size_t)PB*PH*PC*PHD];
__device__ uint32_t g_vt [(size_t)PB*PH*PC*PHD];
__device__ uint32_t g_yt [(size_t)PM*PE];

// ---------------------------------------------------------------------------
// Helpers
// ---------------------------------------------------------------------------
__device__ __forceinline__ uint32_t f2t(float x) {
    uint32_t r;
    asm("cvt.rna.tf32.f32 %0, %1;" : "=r"(r) : "f"(x));
    return r;
}
__device__ __forceinline__ float ex2(float x) {
    float r;
    asm("ex2.approx.f32 %0, %1;" : "=f"(r) : "f"(x));
    return r;
}
__device__ __forceinline__ void mma_tf32(float* c, const uint32_t* a, const uint32_t* b) {
    asm volatile(
        "mma.sync.aligned.m16n8k8.row.col.f32.tf32.tf32.f32 "
        "{%0,%1,%2,%3}, {%4,%5,%6,%7}, {%8,%9}, {%0,%1,%2,%3};"
        : "+f"(c[0]), "+f"(c[1]), "+f"(c[2]), "+f"(c[3])
        : "r"(a[0]), "r"(a[1]), "r"(a[2]), "r"(a[3]), "r"(b[0]), "r"(b[1]));
}
__device__ __forceinline__ void cp16(void* smem_dst, const void* gsrc) {
    uint32_t d = (uint32_t)__cvta_generic_to_shared(smem_dst);
    asm volatile("cp.async.cg.shared.global [%0], [%1], 16;" :: "r"(d), "l"(gsrc));
}
__device__ __forceinline__ void cp_commit() { asm volatile("cp.async.commit_group;"); }
template<int N> __device__ __forceinline__ void cp_wait() {
    asm volatile("cp.async.wait_group %0;" :: "n"(N));
}

// ---------------------------------------------------------------------------
// Pre-pass: fp32 -> tf32 bit-pattern conversion
// ---------------------------------------------------------------------------
__global__ void cvt4_kernel(const float4* __restrict__ src, uint4* __restrict__ dst, int n4)
{
    int i = blockIdx.x * blockDim.x + threadIdx.x;
    if (i < n4) {
        float4 v = src[i];
        dst[i] = make_uint4(f2t(v.x), f2t(v.y), f2t(v.z), f2t(v.w));
    }
}

// ---------------------------------------------------------------------------
// TF32 GEMM (mma.sync): 128x128x32 CTA tile, 8 warps, warp tile 64x32
// Inputs pre-converted tf32 -> hot loop is pure LDS + HMMA.
// As [m][k] pitch 36 (4 mod 32), Bs [k][n] pitch 136 (8 mod 32): conflict-free
// EPI 0: A=g_xt, B=g_wat, scatter head-major tf32 q/k/v
// EPI 1: A=g_yt, B=g_wpt, fp32 C out
// ---------------------------------------------------------------------------
#define APITCH 36
#define BPITCH 136
#define ASZ (128*APITCH)
#define BSZ (32*BPITCH)

template<int N, int EPI>
__global__ __launch_bounds__(256, 2)
void gemm_tf32(float* __restrict__ Cout)
{
    extern __shared__ uint32_t sm[];
    uint32_t* As = sm;               // 2 * ASZ
    uint32_t* Bs = sm + 2 * ASZ;     // 2 * BSZ

    const uint32_t* Ap = EPI ? g_yt  : g_xt;
    const uint32_t* Bp = EPI ? g_wpt : g_wat;
    const int K = PK;

    const int tid = threadIdx.x;
    const int warp = tid >> 5, lane = tid & 31;
    const int l4 = lane >> 2, lq = lane & 3;
    const int wm = (warp & 1) * 64, wn = (warp >> 1) * 32;
    const int bx = blockIdx.x, by = blockIdx.y;

    float acc[4][4][4];
    #pragma unroll
    for (int i = 0; i < 4; i++)
        #pragma unroll
        for (int j = 0; j < 4; j++)
            #pragma unroll
            for (int r = 0; r < 4; r++) acc[i][j][r] = 0.f;

    auto issue = [&](int it) {
        int buf = it & 1;
        int k0 = it * 32;
        uint32_t* Ab = As + buf * ASZ;
        uint32_t* Bb = Bs + buf * BSZ;
        #pragma unroll
        for (int i = 0; i < 4; i++) {
            int idx = tid + i * 256;
            int r = idx >> 3, c4 = (idx & 7) * 4;
            cp16(Ab + r * APITCH + c4, Ap + (size_t)(by * 128 + r) * K + k0 + c4);
        }
        #pragma unroll
        for (int i = 0; i < 4; i++) {
            int idx = tid + i * 256;
            int kr = idx >> 5, c4 = (idx & 31) * 4;
            cp16(Bb + kr * BPITCH + c4, Bp + (size_t)(k0 + kr) * N + bx * 128 + c4);
        }
        cp_commit();
    };

    issue(0);
    const int NIT = K / 32;
    #pragma unroll 1
    for (int it = 0; it < NIT; ++it) {
        if (it + 1 < NIT) { issue(it + 1); cp_wait<1>(); }
        else              { cp_wait<0>(); }
        __syncthreads();
        const uint32_t* Ab = As + (it & 1) * ASZ;
        const uint32_t* Bb = Bs + (it & 1) * BSZ;

        #pragma unroll
        for (int ks = 0; ks < 4; ks++) {
            int k = ks * 8;
            uint32_t a[4][4], b[4][2];
            #pragma unroll
            for (int mt = 0; mt < 4; mt++) {
                int m = wm + mt * 16 + l4;
                a[mt][0] = Ab[m * APITCH + k + lq];
                a[mt][1] = Ab[(m + 8) * APITCH + k + lq];
                a[mt][2] = Ab[m * APITCH + k + 4 + lq];
                a[mt][3] = Ab[(m + 8) * APITCH + k + 4 + lq];
            }
            #pragma unroll
            for (int nt = 0; nt < 4; nt++) {
                int n = wn + nt * 8 + l4;
                b[nt][0] = Bb[(k + lq) * BPITCH + n];
                b[nt][1] = Bb[(k + 4 + lq) * BPITCH + n];
            }
            #pragma unroll
            for (int mt = 0; mt < 4; mt++)
                #pragma unroll
                for (int nt = 0; nt < 4; nt++)
                    mma_tf32(acc[mt][nt], a[mt], b[nt]);
        }
        __syncthreads();
    }

    // Epilogue
    #pragma unroll
    for (int mt = 0; mt < 4; mt++) {
        #pragma unroll
        for (int nt = 0; nt < 4; nt++) {
            int gm = by * 128 + wm + mt * 16 + l4;
            int gn = bx * 128 + wn + nt * 8 + lq * 2;
            if (EPI == 0) {
                int which = gn >> 10;
                int hn = gn & 1023;
                int h = hn >> 6, d = hn & 63;
                uint32_t* dst = (which == 0) ? g_qt : (which == 1 ? g_kt : g_vt);
                int b_ = gm >> 11, c_ = gm & 2047;
                size_t base = (((size_t)(b_ * PH + h)) * PC + c_) * PHD + d;
                *(uint2*)&dst[base] =
                    make_uint2(f2t(acc[mt][nt][0]), f2t(acc[mt][nt][1]));
                *(uint2*)&dst[base + (size_t)8 * PHD] =
                    make_uint2(f2t(acc[mt][nt][2]), f2t(acc[mt][nt][3]));
            } else {
                *(float2*)&Cout[(size_t)gm * N + gn] =
                    make_float2(acc[mt][nt][0], acc[mt][nt][1]);
                *(float2*)&Cout[(size_t)(gm + 8) * N + gn] =
                    make_float2(acc[mt][nt][2], acc[mt][nt][3]);
            }
        }
    }
}

// ---------------------------------------------------------------------------
// Flash attention: CTA = 128 q-rows x (b*h). 8 warps (16 rows each).
// Q fragments persistent in registers (tf32 from g_qt). K/V tf32 via cp.async.
// Softmax in log2 domain; P C->A layout via quad shuffles.
// ---------------------------------------------------------------------------
#define KP 68
#define VP 72
#define KS_SZ (64*KP)
#define VS_SZ (64*VP)

__global__ __launch_bounds__(256, 2)
void attn3()
{
    extern __shared__ uint32_t sm[];
    uint32_t* Ks = sm;                // 2 * KS_SZ
    uint32_t* Vs = sm + 2 * KS_SZ;    // 2 * VS_SZ

    const int qb = (int)gridDim.x - 1 - (int)blockIdx.x;   // big work first
    const int bh = blockIdx.y;
    const uint32_t* Qg = g_qt + (size_t)bh * PC * PHD + (size_t)qb * 128 * PHD;
    const uint32_t* Kg = g_kt + (size_t)bh * PC * PHD;
    const uint32_t* Vg = g_vt + (size_t)bh * PC * PHD;

    const int tid = threadIdx.x;
    const int warp = tid >> 5, lane = tid & 31;
    const int l4 = lane >> 2, lq = lane & 3;
    const int mrow = warp * 16;

    uint32_t aq[8][4];
    {
        const int r0 = mrow + l4, r1 = r0 + 8;
        #pragma unroll
        for (int kt = 0; kt < 8; kt++) {
            int k = kt * 8;
            aq[kt][0] = Qg[r0 * PHD + k + lq];
            aq[kt][1] = Qg[r1 * PHD + k + lq];
            aq[kt][2] = Qg[r0 * PHD + k + 4 + lq];
            aq[kt][3] = Qg[r1 * PHD + k + 4 + lq];
        }
    }

    auto issueKV = [&](int jb) {
        int buf = jb & 1;
        uint32_t* Kb = Ks + buf * KS_SZ;
        uint32_t* Vb = Vs + buf * VS_SZ;
        const uint32_t* kg = Kg + (size_t)jb * 64 * PHD;
        const uint32_t* vg = Vg + (size_t)jb * 64 * PHD;
        #pragma unroll
        for (int i = 0; i < 4; i++) {
            int idx = tid + i * 256;
            int r = idx >> 4, c4 = (idx & 15) * 4;
            cp16(Kb + r * KP + c4, kg + r * PHD + c4);
            cp16(Vb + r * VP + c4, vg + r * PHD + c4);
        }
        cp_commit();
    };

    float o[8][4];
    #pragma unroll
    for (int nt = 0; nt < 8; nt++)
        #pragma unroll
        for (int j = 0; j < 4; j++) o[nt][j] = 0.f;
    float mx0 = -1e30f, mx1 = -1e30f, ls0 = 0.f, ls1 = 0.f;

    const float SC = 0.125f * 1.4426950408889634f;   // 1/sqrt(64) * log2(e)
    const int NJB = 2 * qb + 2;
    const int r0g = qb * 128 + mrow + l4;
    const int r1g = r0g + 8;

    issueKV(0);

    #pragma unroll 1
    for (int jb = 0; jb < NJB; ++jb) {
        if (jb + 1 < NJB) { issueKV(jb + 1); cp_wait<1>(); }
        else              { cp_wait<0>(); }
        __syncthreads();
        const uint32_t* Kb = Ks + (jb & 1) * KS_SZ;
        const uint32_t* Vb = Vs + (jb & 1) * VS_SZ;

        float s[8][4];
        #pragma unroll
        for (int nt = 0; nt < 8; nt++)
            #pragma unroll
            for (int j = 0; j < 4; j++) s[nt][j] = 0.f;

        #pragma unroll
        for (int kt = 0; kt < 8; kt++) {
            int k = kt * 8;
            #pragma unroll
            for (int nt = 0; nt < 8; nt++) {
                uint32_t b[2];
                b[0] = Kb[(nt * 8 + l4) * KP + k + lq];
                b[1] = Kb[(nt * 8 + l4) * KP + k + 4 + lq];
                mma_tf32(s[nt], aq[kt], b);
            }
        }

        #pragma unroll
        for (int nt = 0; nt < 8; nt++)
            #pragma unroll
            for (int j = 0; j < 4; j++) s[nt][j] *= SC;

        if (jb * 64 + 63 > qb * 128 + mrow) {
            #pragma unroll
            for (int nt = 0; nt < 8; nt++) {
                int cn = jb * 64 + nt * 8 + lq * 2;
                if (cn     > r0g) s[nt][0] = -1e30f;
                if (cn + 1 > r0g) s[nt][1] = -1e30f;
                if (cn     > r1g) s[nt][2] = -1e30f;
                if (cn + 1 > r1g) s[nt][3] = -1e30f;
            }
        }

        float rm0 = -1e30f, rm1 = -1e30f;
        #pragma unroll
        for (int nt = 0; nt < 8; nt++) {
            rm0 = fmaxf(rm0, fmaxf(s[nt][0], s[nt][1]));
            rm1 = fmaxf(rm1, fmaxf(s[nt][2], s[nt][3]));
        }
        rm0 = fmaxf(rm0, __shfl_xor_sync(0xffffffffu, rm0, 1));
        rm0 = fmaxf(rm0, __shfl_xor_sync(0xffffffffu, rm0, 2));
        rm1 = fmaxf(rm1, __shfl_xor_sync(0xffffffffu, rm1, 1));
        rm1 = fmaxf(rm1, __shfl_xor_sync(0xffffffffu, rm1, 2));
        float nm0 = fmaxf(mx0, rm0), nm1 = fmaxf(mx1, rm1);
        float al0 = ex2(mx0 - nm0), al1 = ex2(mx1 - nm1);
        float rs0 = 0.f, rs1 = 0.f;
        #pragma unroll
        for (int nt = 0; nt < 8; nt++) {
            s[nt][0] = ex2(s[nt][0] - nm0); rs0 += s[nt][0];
            s[nt][1] = ex2(s[nt][1] - nm0); rs0 += s[nt][1];
            s[nt][2] = ex2(s[nt][2] - nm1); rs1 += s[nt][2];
            s[nt][3] = ex2(s[nt][3] - nm1); rs1 += s[nt][3];
        }
        rs0 += __shfl_xor_sync(0xffffffffu, rs0, 1);
        rs0 += __shfl_xor_sync(0xffffffffu, rs0, 2);
        rs1 += __shfl_xor_sync(0xffffffffu, rs1, 1);
        rs1 += __shfl_xor_sync(0xffffffffu, rs1, 2);
        ls0 = ls0 * al0 + rs0; mx0 = nm0;
        ls1 = ls1 * al1 + rs1; mx1 = nm1;
        #pragma unroll
        for (int nt = 0; nt < 8; nt++) {
            o[nt][0] *= al0; o[nt][1] *= al0;
            o[nt][2] *= al1; o[nt][3] *= al1;
        }

        #pragma unroll
        for (int kt = 0; kt < 8; kt++) {
            int src0 = (lane & ~3) | (lq >> 1);
            int src1 = src0 + 2;
            float v00 = __shfl_sync(0xffffffffu, s[kt][0], src0);
            float v01 = __shfl_sync(0xffffffffu, s[kt][1], src0);
            float v10 = __shfl_sync(0xffffffffu, s[kt][2], src0);
            float v11 = __shfl_sync(0xffffffffu, s[kt][3], src0);
            float w00 = __shfl_sync(0xffffffffu, s[kt][0], src1);
            float w01 = __shfl_sync(0xffffffffu, s[kt][1], src1);
            float w10 = __shfl_sync(0xffffffffu, s[kt][2], src1);
            float w11 = __shfl_sync(0xffffffffu, s[kt][3], src1);
            bool odd = (lq & 1);
            uint32_t a[4];
            a[0] = f2t(odd ? v01 : v00);
            a[1] = f2t(odd ? v11 : v10);
            a[2] = f2t(odd ? w01 : w00);
            a[3] = f2t(odd ? w11 : w10);
            int k = kt * 8;
            #pragma unroll
            for (int nt = 0; nt < 8; nt++) {
                uint32_t b[2];
                b[0] = Vb[(k + lq) * VP + nt * 8 + l4];
                b[1] = Vb[(k + 4 + lq) * VP + nt * 8 + l4];
                mma_tf32(o[nt], a, b);
            }
        }
        __syncthreads();
    }

    int h_ = bh & 15, b_ = bh >> 4;
    float il0 = 1.0f / ls0, il1 = 1.0f / ls1;
    #pragma unroll
    for (int nt = 0; nt < 8; nt++) {
        int d = nt * 8 + lq * 2;
        size_t base = ((size_t)b_ * PC + r0g) * PE + h_ * PHD + d;
        *(uint2*)&g_yt[base] =
            make_uint2(f2t(o[nt][0] * il0), f2t(o[nt][1] * il0));
        *(uint2*)&g_yt[base + (size_t)8 * PE] =
            make_uint2(f2t(o[nt][2] * il1), f2t(o[nt][3] * il1));
    }
}

// ---------------------------------------------------------------------------
extern "C" void kernel_launch(void* const* d_in, const int* in_sizes, int n_in,
                              void* d_out, int out_size)
{
    const float* x  = (const float*)d_in[0];
    const float* Wa = (const float*)d_in[1];
    const float* Wp = (const float*)d_in[2];
    float* out = (float*)d_out;

    size_t smemG = (size_t)(2 * ASZ + 2 * BSZ) * sizeof(uint32_t);     // 71680
    size_t smemA = (size_t)(2 * KS_SZ + 2 * VS_SZ) * sizeof(uint32_t); // 71680

    cudaFuncSetAttribute(gemm_tf32<PN3, 0>,
                         cudaFuncAttributeMaxDynamicSharedMemorySize, (int)smemG);
    cudaFuncSetAttribute(gemm_tf32<PE, 1>,
                         cudaFuncAttributeMaxDynamicSharedMemorySize, (int)smemG);
    cudaFuncSetAttribute(attn3,
                         cudaFuncAttributeMaxDynamicSharedMemorySize, (int)smemA);

    // Pre-pass: fp32 -> tf32 bit patterns
    uint4* d_xt;  cudaGetSymbolAddress((void**)&d_xt,  g_xt);
    uint4* d_wat; cudaGetSymbolAddress((void**)&d_wat, g_wat);
    uint4* d_wpt; cudaGetSymbolAddress((void**)&d_wpt, g_wpt);
    {
        int n4 = PM * PK / 4;
        cvt4_kernel<<<(n4 + 255) / 256, 256>>>((const float4*)x, d_xt, n4);
        n4 = PK * PN3 / 4;
        cvt4_kernel<<<(n4 + 255) / 256, 256>>>((const float4*)Wa, d_wat, n4);
        n4 = PK * PE / 4;
        cvt4_kernel<<<(n4 + 255) / 256, 256>>>((const float4*)Wp, d_wpt, n4);
    }

    gemm_tf32<PN3, 0><<<dim3(PN3 / 128, PM / 128), 256, smemG>>>(nullptr);
    attn3<<<dim3(PC / 128, PB * PH), 256, smemA>>>();
    gemm_tf32<PE, 1><<<dim3(PE / 128, PM / 128), 256, smemG>>>(out);
}

// round 6
// speedup vs baseline: 2.0045x; 1.9333x over previous
#include <cuda_runtime.h>
#include <cuda_fp16.h>
#include <cstdint>

#define PB 4
#define PC 2048
#define PE 1024
#define PH 16
#define PHD 64
#define PM (PB*PC)        // 8192
#define PK PE             // 1024
#define PN3 (3*PE)        // 3072

// fp16 scratch (device globals: allocation-free rule)
__device__ __half g_xh  [(size_t)PM*PK];
__device__ __half g_watT[(size_t)PN3*PK];   // W_attn^T [3072][1024]
__device__ __half g_wptT[(size_t)PE*PK];    // W_proj^T [1024][1024]
__device__ __half g_qh  [(size_t)PB*PH*PC*PHD];
__device__ __half g_kh  [(size_t)PB*PH*PC*PHD];
__device__ __half g_vh  [(size_t)PB*PH*PC*PHD];
__device__ __half g_yh  [(size_t)PM*PE];

// ---------------------------------------------------------------------------
// Helpers
// ---------------------------------------------------------------------------
__device__ __forceinline__ float ex2(float x) {
    float r;
    asm("ex2.approx.f32 %0, %1;" : "=f"(r) : "f"(x));
    return r;
}
__device__ __forceinline__ uint32_t packh2(float lo, float hi) {
    __half2 p = __floats2half2_rn(lo, hi);
    return *(uint32_t*)&p;
}
__device__ __forceinline__ void mma_f16(float* c, const uint32_t* a, const uint32_t* b) {
    asm volatile(
        "mma.sync.aligned.m16n8k16.row.col.f32.f16.f16.f32 "
        "{%0,%1,%2,%3}, {%4,%5,%6,%7}, {%8,%9}, {%0,%1,%2,%3};"
        : "+f"(c[0]), "+f"(c[1]), "+f"(c[2]), "+f"(c[3])
        : "r"(a[0]), "r"(a[1]), "r"(a[2]), "r"(a[3]), "r"(b[0]), "r"(b[1]));
}
__device__ __forceinline__ void ldsm4t(uint32_t& r0, uint32_t& r1,
                                       uint32_t& r2, uint32_t& r3, uint32_t addr) {
    asm volatile("ldmatrix.sync.aligned.m8n8.x4.trans.shared.b16 {%0,%1,%2,%3}, [%4];"
                 : "=r"(r0), "=r"(r1), "=r"(r2), "=r"(r3) : "r"(addr));
}
__device__ __forceinline__ void cp16(void* smem_dst, const void* gsrc) {
    uint32_t d = (uint32_t)__cvta_generic_to_shared(smem_dst);
    asm volatile("cp.async.cg.shared.global [%0], [%1], 16;" :: "r"(d), "l"(gsrc));
}
__device__ __forceinline__ void cp_commit() { asm volatile("cp.async.commit_group;"); }
template<int N> __device__ __forceinline__ void cp_wait() {
    asm volatile("cp.async.wait_group %0;" :: "n"(N));
}

// ---------------------------------------------------------------------------
// Pre-pass: fp32 -> fp16
// ---------------------------------------------------------------------------
__global__ void cvt_h4(const float4* __restrict__ src, uint2* __restrict__ dst, int n4)
{
    int i = blockIdx.x * blockDim.x + threadIdx.x;
    if (i < n4) {
        float4 v = src[i];
        dst[i] = make_uint2(packh2(v.x, v.y), packh2(v.z, v.w));
    }
}

// src [Ksrc][Nsrc] fp32 -> dst [Nsrc][Ksrc] fp16
__global__ void transpose_h(const float* __restrict__ src, __half* __restrict__ dst,
                            int Ksrc, int Nsrc)
{
    __shared__ __half t[32][33];
    int bx = blockIdx.x, by = blockIdx.y;
    int tx = threadIdx.x, ty = threadIdx.y;    // (32, 8)
    #pragma unroll
    for (int j = 0; j < 4; j++) {
        int y = by * 32 + ty + j * 8;
        t[ty + j * 8][tx] = __float2half_rn(src[(size_t)y * Nsrc + bx * 32 + tx]);
    }
    __syncthreads();
    #pragma unroll
    for (int j = 0; j < 4; j++) {
        int n = bx * 32 + ty + j * 8;
        dst[(size_t)n * Ksrc + by * 32 + tx] = t[tx][ty + j * 8];
    }
}

// ---------------------------------------------------------------------------
// FP16 GEMM (m16n8k16): CTA 128x128, BK=64, 8 warps, warp tile 64x32
// A [m][k], B^T [n][k] both K-major fp16, smem pitch 72 halves (conflict-free)
// EPI 0: A=g_xh, B=g_watT -> scatter fp16 q/k/v head-major
// EPI 1: A=g_yh, B=g_wptT -> fp32 out
// ---------------------------------------------------------------------------
#define GP 72
#define GSZ (128*GP)      // halves per operand buffer

template<int N, int EPI>
__global__ __launch_bounds__(256, 2)
void gemm_h(float* __restrict__ Cout)
{
    extern __shared__ __half sh[];
    __half* As = sh;                 // 2 * GSZ
    __half* Bs = sh + 2 * GSZ;       // 2 * GSZ

    const __half* Ap = EPI ? g_yh   : g_xh;
    const __half* Bp = EPI ? g_wptT : g_watT;
    const int K = PK;

    const int tid = threadIdx.x;
    const int warp = tid >> 5, lane = tid & 31;
    const int l4 = lane >> 2, lq = lane & 3;
    const int wm = (warp & 1) * 64, wn = (warp >> 1) * 32;
    const int bx = blockIdx.x, by = blockIdx.y;

    float acc[4][4][4];
    #pragma unroll
    for (int i = 0; i < 4; i++)
        #pragma unroll
        for (int j = 0; j < 4; j++)
            #pragma unroll
            for (int r = 0; r < 4; r++) acc[i][j][r] = 0.f;

    auto issue = [&](int it) {
        int buf = it & 1;
        int k0 = it * 64;
        __half* Ab = As + buf * GSZ;
        __half* Bb = Bs + buf * GSZ;
        #pragma unroll
        for (int i = 0; i < 4; i++) {
            int idx = tid + i * 256;
            int r = idx >> 3, c = idx & 7;            // 8 chunks of 8 halves
            cp16(Ab + r * GP + c * 8, Ap + (size_t)(by * 128 + r) * K + k0 + c * 8);
        }
        #pragma unroll
        for (int i = 0; i < 4; i++) {
            int idx = tid + i * 256;
            int r = idx >> 3, c = idx & 7;
            cp16(Bb + r * GP + c * 8, Bp + (size_t)(bx * 128 + r) * K + k0 + c * 8);
        }
        cp_commit();
    };

    issue(0);
    const int NIT = K / 64;
    #pragma unroll 1
    for (int it = 0; it < NIT; ++it) {
        if (it + 1 < NIT) { issue(it + 1); cp_wait<1>(); }
        else              { cp_wait<0>(); }
        __syncthreads();
        const __half* Ab = As + (it & 1) * GSZ;
        const __half* Bb = Bs + (it & 1) * GSZ;

        #pragma unroll
        for (int ks = 0; ks < 4; ks++) {
            int k = ks * 16;
            uint32_t a[4][4], b[4][2];
            #pragma unroll
            for (int mt = 0; mt < 4; mt++) {
                int m = wm + mt * 16 + l4;
                a[mt][0] = *(const uint32_t*)&Ab[m * GP + k + 2 * lq];
                a[mt][1] = *(const uint32_t*)&Ab[(m + 8) * GP + k + 2 * lq];
                a[mt][2] = *(const uint32_t*)&Ab[m * GP + k + 8 + 2 * lq];
                a[mt][3] = *(const uint32_t*)&Ab[(m + 8) * GP + k + 8 + 2 * lq];
            }
            #pragma unroll
            for (int nt = 0; nt < 4; nt++) {
                int n = wn + nt * 8 + l4;
                b[nt][0] = *(const uint32_t*)&Bb[n * GP + k + 2 * lq];
                b[nt][1] = *(const uint32_t*)&Bb[n * GP + k + 8 + 2 * lq];
            }
            #pragma unroll
            for (int mt = 0; mt < 4; mt++)
                #pragma unroll
                for (int nt = 0; nt < 4; nt++)
                    mma_f16(acc[mt][nt], a[mt], b[nt]);
        }
        __syncthreads();
    }

    // Epilogue
    #pragma unroll
    for (int mt = 0; mt < 4; mt++) {
        #pragma unroll
        for (int nt = 0; nt < 4; nt++) {
            int gm = by * 128 + wm + mt * 16 + l4;
            int gn = bx * 128 + wn + nt * 8 + lq * 2;
            if (EPI == 0) {
                int which = gn >> 10;
                int hn = gn & 1023;
                int h = hn >> 6, d = hn & 63;
                __half* dst = (which == 0) ? g_qh : (which == 1 ? g_kh : g_vh);
                int b_ = gm >> 11, c_ = gm & 2047;
                size_t base = (((size_t)(b_ * PH + h)) * PC + c_) * PHD + d;
                *(uint32_t*)&dst[base] = packh2(acc[mt][nt][0], acc[mt][nt][1]);
                *(uint32_t*)&dst[base + (size_t)8 * PHD] =
                    packh2(acc[mt][nt][2], acc[mt][nt][3]);
            } else {
                *(float2*)&Cout[(size_t)gm * N + gn] =
                    make_float2(acc[mt][nt][0], acc[mt][nt][1]);
                *(float2*)&Cout[(size_t)(gm + 8) * N + gn] =
                    make_float2(acc[mt][nt][2], acc[mt][nt][3]);
            }
        }
    }
}

// ---------------------------------------------------------------------------
// FP16 flash attention: CTA = 128 q-rows x (b*h), 8 warps (16 rows each).
// Persistent Q frags; K b-frags direct LDS; V via ldmatrix.x4.trans;
// P reuses S C-layout as A-layout (no shuffles). Pitch 72 halves.
// ---------------------------------------------------------------------------
#define KVP 72
#define KV_SZ (64*KVP)    // halves

__global__ __launch_bounds__(256, 2)
void attn_h()
{
    extern __shared__ __half sh[];
    __half* Ks = sh;                 // 2 * KV_SZ
    __half* Vs = sh + 2 * KV_SZ;     // 2 * KV_SZ

    const int qb = (int)gridDim.x - 1 - (int)blockIdx.x;   // big work first
    const int bh = blockIdx.y;
    const __half* Qg = g_qh + (size_t)bh * PC * PHD + (size_t)qb * 128 * PHD;
    const __half* Kg = g_kh + (size_t)bh * PC * PHD;
    const __half* Vg = g_vh + (size_t)bh * PC * PHD;

    const int tid = threadIdx.x;
    const int warp = tid >> 5, lane = tid & 31;
    const int l4 = lane >> 2, lq = lane & 3;
    const int mrow = warp * 16;

    // Persistent Q fragments: aq[kt][0..3], kt over K=64 in 16-chunks
    uint32_t aq[4][4];
    {
        const int r0 = mrow + l4, r1 = r0 + 8;
        #pragma unroll
        for (int kt = 0; kt < 4; kt++) {
            int k = kt * 16;
            aq[kt][0] = *(const uint32_t*)&Qg[r0 * PHD + k + 2 * lq];
            aq[kt][1] = *(const uint32_t*)&Qg[r1 * PHD + k + 2 * lq];
            aq[kt][2] = *(const uint32_t*)&Qg[r0 * PHD + k + 8 + 2 * lq];
            aq[kt][3] = *(const uint32_t*)&Qg[r1 * PHD + k + 8 + 2 * lq];
        }
    }

    auto issueKV = [&](int jb) {
        int buf = jb & 1;
        __half* Kb = Ks + buf * KV_SZ;
        __half* Vb = Vs + buf * KV_SZ;
        const __half* kg = Kg + (size_t)jb * 64 * PHD;
        const __half* vg = Vg + (size_t)jb * 64 * PHD;
        #pragma unroll
        for (int i = 0; i < 2; i++) {
            int idx = tid + i * 256;
            int r = idx >> 3, c = idx & 7;            // 64 rows x 8 chunks
            cp16(Kb + r * KVP + c * 8, kg + r * PHD + c * 8);
            cp16(Vb + r * KVP + c * 8, vg + r * PHD + c * 8);
        }
        cp_commit();
    };

    float o[8][4];
    #pragma unroll
    for (int nt = 0; nt < 8; nt++)
        #pragma unroll
        for (int j = 0; j < 4; j++) o[nt][j] = 0.f;
    float mx0 = -1e30f, mx1 = -1e30f, ls0 = 0.f, ls1 = 0.f;

    const float SC = 0.125f * 1.4426950408889634f;   // 1/sqrt(64) * log2(e)
    const int NJB = 2 * qb + 2;
    const int r0g = qb * 128 + mrow + l4;
    const int r1g = r0g + 8;

    // per-lane ldmatrix address term: row (lane&15), col-half (lane&16)
    const int vlane = (lane & 15) * (KVP * 2) + (lane & 16);

    issueKV(0);

    #pragma unroll 1
    for (int jb = 0; jb < NJB; ++jb) {
        if (jb + 1 < NJB) { issueKV(jb + 1); cp_wait<1>(); }
        else              { cp_wait<0>(); }
        __syncthreads();
        const __half* Kb = Ks + (jb & 1) * KV_SZ;
        const __half* Vb = Vs + (jb & 1) * KV_SZ;
        uint32_t vbase = (uint32_t)__cvta_generic_to_shared(Vb) + vlane;

        // S = Q K^T
        float s[8][4];
        #pragma unroll
        for (int nt = 0; nt < 8; nt++)
            #pragma unroll
            for (int j = 0; j < 4; j++) s[nt][j] = 0.f;

        #pragma unroll
        for (int kt = 0; kt < 4; kt++) {
            int k = kt * 16;
            #pragma unroll
            for (int nt = 0; nt < 8; nt++) {
                uint32_t b[2];
                b[0] = *(const uint32_t*)&Kb[(nt * 8 + l4) * KVP + k + 2 * lq];
                b[1] = *(const uint32_t*)&Kb[(nt * 8 + l4) * KVP + k + 8 + 2 * lq];
                mma_f16(s[nt], aq[kt], b);
            }
        }

        // scale (log2 domain) + causal mask
        #pragma unroll
        for (int nt = 0; nt < 8; nt++)
            #pragma unroll
            for (int j = 0; j < 4; j++) s[nt][j] *= SC;

        if (jb * 64 + 63 > qb * 128 + mrow) {
            #pragma unroll
            for (int nt = 0; nt < 8; nt++) {
                int cn = jb * 64 + nt * 8 + lq * 2;
                if (cn     > r0g) s[nt][0] = -1e30f;
                if (cn + 1 > r0g) s[nt][1] = -1e30f;
                if (cn     > r1g) s[nt][2] = -1e30f;
                if (cn + 1 > r1g) s[nt][3] = -1e30f;
            }
        }

        // online softmax
        float rm0 = -1e30f, rm1 = -1e30f;
        #pragma unroll
        for (int nt = 0; nt < 8; nt++) {
            rm0 = fmaxf(rm0, fmaxf(s[nt][0], s[nt][1]));
            rm1 = fmaxf(rm1, fmaxf(s[nt][2], s[nt][3]));
        }
        rm0 = fmaxf(rm0, __shfl_xor_sync(0xffffffffu, rm0, 1));
        rm0 = fmaxf(rm0, __shfl_xor_sync(0xffffffffu, rm0, 2));
        rm1 = fmaxf(rm1, __shfl_xor_sync(0xffffffffu, rm1, 1));
        rm1 = fmaxf(rm1, __shfl_xor_sync(0xffffffffu, rm1, 2));
        float nm0 = fmaxf(mx0, rm0), nm1 = fmaxf(mx1, rm1);
        float al0 = ex2(mx0 - nm0), al1 = ex2(mx1 - nm1);
        float rs0 = 0.f, rs1 = 0.f;
        #pragma unroll
        for (int nt = 0; nt < 8; nt++) {
            s[nt][0] = ex2(s[nt][0] - nm0); rs0 += s[nt][0];
            s[nt][1] = ex2(s[nt][1] - nm0); rs0 += s[nt][1];
            s[nt][2] = ex2(s[nt][2] - nm1); rs1 += s[nt][2];
            s[nt][3] = ex2(s[nt][3] - nm1); rs1 += s[nt][3];
        }
        rs0 += __shfl_xor_sync(0xffffffffu, rs0, 1);
        rs0 += __shfl_xor_sync(0xffffffffu, rs0, 2);
        rs1 += __shfl_xor_sync(0xffffffffu, rs1, 1);
        rs1 += __shfl_xor_sync(0xffffffffu, rs1, 2);
        ls0 = ls0 * al0 + rs0; mx0 = nm0;
        ls1 = ls1 * al1 + rs1; mx1 = nm1;
        #pragma unroll
        for (int nt = 0; nt < 8; nt++) {
            o[nt][0] *= al0; o[nt][1] *= al0;
            o[nt][2] *= al1; o[nt][3] *= al1;
        }

        // O += P @ V : P (C-layout) == A-layout for fp16 mma; V via ldmatrix.trans
        #pragma unroll
        for (int kp = 0; kp < 4; kp++) {
            uint32_t ap[4];
            ap[0] = packh2(s[2 * kp][0],     s[2 * kp][1]);
            ap[1] = packh2(s[2 * kp][2],     s[2 * kp][3]);
            ap[2] = packh2(s[2 * kp + 1][0], s[2 * kp + 1][1]);
            ap[3] = packh2(s[2 * kp + 1][2], s[2 * kp + 1][3]);
            uint32_t kaddr = vbase + kp * 16 * (KVP * 2);
            #pragma unroll
            for (int g = 0; g < 4; g++) {
                uint32_t b0, b1, b2, b3;
                ldsm4t(b0, b1, b2, b3, kaddr + g * 32);
                uint32_t bl[2] = {b0, b1}, bh2[2] = {b2, b3};
                mma_f16(o[2 * g],     ap, bl);
                mma_f16(o[2 * g + 1], ap, bh2);
            }
        }
        __syncthreads();
    }

    // Epilogue: write y (fp16) in [B,C,E], e = h*64 + d
    int h_ = bh & 15, b_ = bh >> 4;
    float il0 = 1.0f / ls0, il1 = 1.0f / ls1;
    #pragma unroll
    for (int nt = 0; nt < 8; nt++) {
        int d = nt * 8 + lq * 2;
        size_t base = ((size_t)b_ * PC + r0g) * PE + h_ * PHD + d;
        *(uint32_t*)&g_yh[base] = packh2(o[nt][0] * il0, o[nt][1] * il0);
        *(uint32_t*)&g_yh[base + (size_t)8 * PE] = packh2(o[nt][2] * il1, o[nt][3] * il1);
    }
}

// ---------------------------------------------------------------------------
extern "C" void kernel_launch(void* const* d_in, const int* in_sizes, int n_in,
                              void* d_out, int out_size)
{
    const float* x  = (const float*)d_in[0];
    const float* Wa = (const float*)d_in[1];
    const float* Wp = (const float*)d_in[2];
    float* out = (float*)d_out;

    size_t smemG = (size_t)4 * GSZ * sizeof(__half);     // 73728
    size_t smemA = (size_t)4 * KV_SZ * sizeof(__half);   // 36864

    cudaFuncSetAttribute(gemm_h<PN3, 0>,
                         cudaFuncAttributeMaxDynamicSharedMemorySize, (int)smemG);
    cudaFuncSetAttribute(gemm_h<PE, 1>,
                         cudaFuncAttributeMaxDynamicSharedMemorySize, (int)smemG);
    cudaFuncSetAttribute(attn_h,
                         cudaFuncAttributeMaxDynamicSharedMemorySize, (int)smemA);

    // Pre-pass: x -> fp16; W_attn, W_proj -> transposed fp16
    uint2* d_xh;    cudaGetSymbolAddress((void**)&d_xh,  g_xh);
    __half* d_watT; cudaGetSymbolAddress((void**)&d_watT, g_watT);
    __half* d_wptT; cudaGetSymbolAddress((void**)&d_wptT, g_wptT);
    {
        int n4 = PM * PK / 4;
        cvt_h4<<<(n4 + 255) / 256, 256>>>((const float4*)x, d_xh, n4);
        transpose_h<<<dim3(PN3 / 32, PK / 32), dim3(32, 8)>>>(Wa, d_watT, PK, PN3);
        transpose_h<<<dim3(PE / 32, PK / 32), dim3(32, 8)>>>(Wp, d_wptT, PK, PE);
    }

    gemm_h<PN3, 0><<<dim3(PN3 / 128, PM / 128), 256, smemG>>>(nullptr);
    attn_h<<<dim3(PC / 128, PB * PH), 256, smemA>>>();
    gemm_h<PE, 1><<<dim3(PE / 128, PM / 128), 256, smemG>>>(out);
}

// round 7
// speedup vs baseline: 2.0819x; 1.0386x over previous
#include <cuda_runtime.h>
#include <cuda_fp16.h>
#include <cstdint>

#define PB 4
#define PC 2048
#define PE 1024
#define PH 16
#define PHD 64
#define PM (PB*PC)        // 8192
#define PK PE             // 1024
#define PN3 (3*PE)        // 3072

// fp16 scratch (device globals: allocation-free rule)
__device__ __half g_xh  [(size_t)PM*PK];
__device__ __half g_watT[(size_t)PN3*PK];   // W_attn^T [3072][1024]
__device__ __half g_wptT[(size_t)PE*PK];    // W_proj^T [1024][1024]
__device__ __half g_qh  [(size_t)PB*PH*PC*PHD];
__device__ __half g_kh  [(size_t)PB*PH*PC*PHD];
__device__ __half g_vh  [(size_t)PB*PH*PC*PHD];
__device__ __half g_yh  [(size_t)PM*PE];

// ---------------------------------------------------------------------------
// Helpers
// ---------------------------------------------------------------------------
__device__ __forceinline__ float ex2(float x) {
    float r;
    asm("ex2.approx.f32 %0, %1;" : "=f"(r) : "f"(x));
    return r;
}
__device__ __forceinline__ uint32_t packh2(float lo, float hi) {
    __half2 p = __floats2half2_rn(lo, hi);
    return *(uint32_t*)&p;
}
__device__ __forceinline__ void mma_f16(float* c, const uint32_t* a, const uint32_t* b) {
    asm volatile(
        "mma.sync.aligned.m16n8k16.row.col.f32.f16.f16.f32 "
        "{%0,%1,%2,%3}, {%4,%5,%6,%7}, {%8,%9}, {%0,%1,%2,%3};"
        : "+f"(c[0]), "+f"(c[1]), "+f"(c[2]), "+f"(c[3])
        : "r"(a[0]), "r"(a[1]), "r"(a[2]), "r"(a[3]), "r"(b[0]), "r"(b[1]));
}
__device__ __forceinline__ void ldsm4t(uint32_t& r0, uint32_t& r1,
                                       uint32_t& r2, uint32_t& r3, uint32_t addr) {
    asm volatile("ldmatrix.sync.aligned.m8n8.x4.trans.shared.b16 {%0,%1,%2,%3}, [%4];"
                 : "=r"(r0), "=r"(r1), "=r"(r2), "=r"(r3) : "r"(addr));
}
__device__ __forceinline__ void cp16(void* smem_dst, const void* gsrc) {
    uint32_t d = (uint32_t)__cvta_generic_to_shared(smem_dst);
    asm volatile("cp.async.cg.shared.global [%0], [%1], 16;" :: "r"(d), "l"(gsrc));
}
__device__ __forceinline__ void cp_commit() { asm volatile("cp.async.commit_group;"); }
template<int N> __device__ __forceinline__ void cp_wait() {
    asm volatile("cp.async.wait_group %0;" :: "n"(N));
}

// ---------------------------------------------------------------------------
// Pre-pass: fp32 -> fp16
// ---------------------------------------------------------------------------
__global__ void cvt_h4(const float4* __restrict__ src, uint2* __restrict__ dst, int n4)
{
    int i = blockIdx.x * blockDim.x + threadIdx.x;
    if (i < n4) {
        float4 v = src[i];
        dst[i] = make_uint2(packh2(v.x, v.y), packh2(v.z, v.w));
    }
}

// src [Ksrc][Nsrc] fp32 -> dst [Nsrc][Ksrc] fp16
__global__ void transpose_h(const float* __restrict__ src, __half* __restrict__ dst,
                            int Ksrc, int Nsrc)
{
    __shared__ __half t[32][33];
    int bx = blockIdx.x, by = blockIdx.y;
    int tx = threadIdx.x, ty = threadIdx.y;    // (32, 8)
    #pragma unroll
    for (int j = 0; j < 4; j++) {
        int y = by * 32 + ty + j * 8;
        t[ty + j * 8][tx] = __float2half_rn(src[(size_t)y * Nsrc + bx * 32 + tx]);
    }
    __syncthreads();
    #pragma unroll
    for (int j = 0; j < 4; j++) {
        int n = bx * 32 + ty + j * 8;
        dst[(size_t)n * Ksrc + by * 32 + tx] = t[tx][ty + j * 8];
    }
}

// ---------------------------------------------------------------------------
// FP16 GEMM: CTA 128x128, BK=64, 4 warps, warp tile 64x64 (2x2 warp grid)
// Fragment traffic: 96KB/iter (vs 128KB at 64x32) -> tensor-bound
// EPI 0: A=g_xh, B=g_watT -> scatter fp16 q/k/v head-major
// EPI 1: A=g_yh, B=g_wptT -> fp32 out
// ---------------------------------------------------------------------------
#define GP 72
#define GSZ (128*GP)      // halves per operand buffer

template<int N, int EPI>
__global__ __launch_bounds__(128, 2)
void gemm_h(float* __restrict__ Cout)
{
    extern __shared__ __half sh[];
    __half* As = sh;                 // 2 * GSZ
    __half* Bs = sh + 2 * GSZ;       // 2 * GSZ

    const __half* Ap = EPI ? g_yh   : g_xh;
    const __half* Bp = EPI ? g_wptT : g_watT;
    const int K = PK;

    const int tid = threadIdx.x;
    const int warp = tid >> 5, lane = tid & 31;
    const int l4 = lane >> 2, lq = lane & 3;
    const int wm = (warp >> 1) * 64, wn = (warp & 1) * 64;
    const int bx = blockIdx.x, by = blockIdx.y;

    float acc[4][8][4];
    #pragma unroll
    for (int i = 0; i < 4; i++)
        #pragma unroll
        for (int j = 0; j < 8; j++)
            #pragma unroll
            for (int r = 0; r < 4; r++) acc[i][j][r] = 0.f;

    auto issue = [&](int it) {
        int buf = it & 1;
        int k0 = it * 64;
        __half* Ab = As + buf * GSZ;
        __half* Bb = Bs + buf * GSZ;
        #pragma unroll
        for (int i = 0; i < 8; i++) {
            int idx = tid + i * 128;
            int r = idx >> 3, c = idx & 7;
            cp16(Ab + r * GP + c * 8, Ap + (size_t)(by * 128 + r) * K + k0 + c * 8);
        }
        #pragma unroll
        for (int i = 0; i < 8; i++) {
            int idx = tid + i * 128;
            int r = idx >> 3, c = idx & 7;
            cp16(Bb + r * GP + c * 8, Bp + (size_t)(bx * 128 + r) * K + k0 + c * 8);
        }
        cp_commit();
    };

    issue(0);
    const int NIT = K / 64;
    #pragma unroll 1
    for (int it = 0; it < NIT; ++it) {
        if (it + 1 < NIT) { issue(it + 1); cp_wait<1>(); }
        else              { cp_wait<0>(); }
        __syncthreads();
        const __half* Ab = As + (it & 1) * GSZ;
        const __half* Bb = Bs + (it & 1) * GSZ;

        #pragma unroll
        for (int ks = 0; ks < 4; ks++) {
            int k = ks * 16;
            uint32_t a[4][4], b[8][2];
            #pragma unroll
            for (int mt = 0; mt < 4; mt++) {
                int m = wm + mt * 16 + l4;
                a[mt][0] = *(const uint32_t*)&Ab[m * GP + k + 2 * lq];
                a[mt][1] = *(const uint32_t*)&Ab[(m + 8) * GP + k + 2 * lq];
                a[mt][2] = *(const uint32_t*)&Ab[m * GP + k + 8 + 2 * lq];
                a[mt][3] = *(const uint32_t*)&Ab[(m + 8) * GP + k + 8 + 2 * lq];
            }
            #pragma unroll
            for (int nt = 0; nt < 8; nt++) {
                int n = wn + nt * 8 + l4;
                b[nt][0] = *(const uint32_t*)&Bb[n * GP + k + 2 * lq];
                b[nt][1] = *(const uint32_t*)&Bb[n * GP + k + 8 + 2 * lq];
            }
            #pragma unroll
            for (int mt = 0; mt < 4; mt++)
                #pragma unroll
                for (int nt = 0; nt < 8; nt++)
                    mma_f16(acc[mt][nt], a[mt], b[nt]);
        }
        __syncthreads();
    }

    // Epilogue
    #pragma unroll
    for (int mt = 0; mt < 4; mt++) {
        #pragma unroll
        for (int nt = 0; nt < 8; nt++) {
            int gm = by * 128 + wm + mt * 16 + l4;
            int gn = bx * 128 + wn + nt * 8 + lq * 2;
            if (EPI == 0) {
                int which = gn >> 10;
                int hn = gn & 1023;
                int h = hn >> 6, d = hn & 63;
                __half* dst = (which == 0) ? g_qh : (which == 1 ? g_kh : g_vh);
                int b_ = gm >> 11, c_ = gm & 2047;
                size_t base = (((size_t)(b_ * PH + h)) * PC + c_) * PHD + d;
                *(uint32_t*)&dst[base] = packh2(acc[mt][nt][0], acc[mt][nt][1]);
                *(uint32_t*)&dst[base + (size_t)8 * PHD] =
                    packh2(acc[mt][nt][2], acc[mt][nt][3]);
            } else {
                *(float2*)&Cout[(size_t)gm * N + gn] =
                    make_float2(acc[mt][nt][0], acc[mt][nt][1]);
                *(float2*)&Cout[(size_t)(gm + 8) * N + gn] =
                    make_float2(acc[mt][nt][2], acc[mt][nt][3]);
            }
        }
    }
}

// ---------------------------------------------------------------------------
// FP16 flash attention: CTA = 128 q-rows, 4 warps x 32 rows (2 m-tiles each).
// Persistent Q frags; V ldmatrix shared across both m-tiles.
// ---------------------------------------------------------------------------
#define KVP 72
#define KV_SZ (64*KVP)    // halves

__global__ __launch_bounds__(128, 2)
void attn_h()
{
    extern __shared__ __half sh[];
    __half* Ks = sh;                 // 2 * KV_SZ
    __half* Vs = sh + 2 * KV_SZ;     // 2 * KV_SZ

    const int qb = (int)gridDim.x - 1 - (int)blockIdx.x;   // big work first
    const int bh = blockIdx.y;
    const __half* Qg = g_qh + (size_t)bh * PC * PHD + (size_t)qb * 128 * PHD;
    const __half* Kg = g_kh + (size_t)bh * PC * PHD;
    const __half* Vg = g_vh + (size_t)bh * PC * PHD;

    const int tid = threadIdx.x;
    const int warp = tid >> 5, lane = tid & 31;
    const int l4 = lane >> 2, lq = lane & 3;
    const int mrow = warp * 32;

    // Persistent Q fragments: aq[mt][kt][0..3]
    uint32_t aq[2][4][4];
    #pragma unroll
    for (int mt = 0; mt < 2; mt++) {
        const int r0 = mrow + mt * 16 + l4, r1 = r0 + 8;
        #pragma unroll
        for (int kt = 0; kt < 4; kt++) {
            int k = kt * 16;
            aq[mt][kt][0] = *(const uint32_t*)&Qg[r0 * PHD + k + 2 * lq];
            aq[mt][kt][1] = *(const uint32_t*)&Qg[r1 * PHD + k + 2 * lq];
            aq[mt][kt][2] = *(const uint32_t*)&Qg[r0 * PHD + k + 8 + 2 * lq];
            aq[mt][kt][3] = *(const uint32_t*)&Qg[r1 * PHD + k + 8 + 2 * lq];
        }
    }

    auto issueKV = [&](int jb) {
        int buf = jb & 1;
        __half* Kb = Ks + buf * KV_SZ;
        __half* Vb = Vs + buf * KV_SZ;
        const __half* kg = Kg + (size_t)jb * 64 * PHD;
        const __half* vg = Vg + (size_t)jb * 64 * PHD;
        #pragma unroll
        for (int i = 0; i < 4; i++) {
            int idx = tid + i * 128;
            int r = idx >> 3, c = idx & 7;
            cp16(Kb + r * KVP + c * 8, kg + r * PHD + c * 8);
            cp16(Vb + r * KVP + c * 8, vg + r * PHD + c * 8);
        }
        cp_commit();
    };

    float o[2][8][4];
    #pragma unroll
    for (int mt = 0; mt < 2; mt++)
        #pragma unroll
        for (int nt = 0; nt < 8; nt++)
            #pragma unroll
            for (int j = 0; j < 4; j++) o[mt][nt][j] = 0.f;
    float mx[2][2], ls[2][2];
    #pragma unroll
    for (int mt = 0; mt < 2; mt++) {
        mx[mt][0] = -1e30f; mx[mt][1] = -1e30f;
        ls[mt][0] = 0.f;    ls[mt][1] = 0.f;
    }

    const float SC = 0.125f * 1.4426950408889634f;   // 1/sqrt(64) * log2(e)
    const int NJB = 2 * qb + 2;

    // per-lane ldmatrix address term
    const int vlane = (lane & 15) * (KVP * 2) + (lane & 16);

    issueKV(0);

    #pragma unroll 1
    for (int jb = 0; jb < NJB; ++jb) {
        if (jb + 1 < NJB) { issueKV(jb + 1); cp_wait<1>(); }
        else              { cp_wait<0>(); }
        __syncthreads();
        const __half* Kb = Ks + (jb & 1) * KV_SZ;
        const __half* Vb = Vs + (jb & 1) * KV_SZ;
        uint32_t vbase = (uint32_t)__cvta_generic_to_shared(Vb) + vlane;

        // S = Q K^T
        float s[2][8][4];
        #pragma unroll
        for (int mt = 0; mt < 2; mt++)
            #pragma unroll
            for (int nt = 0; nt < 8; nt++)
                #pragma unroll
                for (int j = 0; j < 4; j++) s[mt][nt][j] = 0.f;

        #pragma unroll
        for (int kt = 0; kt < 4; kt++) {
            int k = kt * 16;
            #pragma unroll
            for (int nt = 0; nt < 8; nt++) {
                uint32_t b[2];
                b[0] = *(const uint32_t*)&Kb[(nt * 8 + l4) * KVP + k + 2 * lq];
                b[1] = *(const uint32_t*)&Kb[(nt * 8 + l4) * KVP + k + 8 + 2 * lq];
                mma_f16(s[0][nt], aq[0][kt], b);
                mma_f16(s[1][nt], aq[1][kt], b);
            }
        }

        // scale (log2 domain) + causal mask
        #pragma unroll
        for (int mt = 0; mt < 2; mt++)
            #pragma unroll
            for (int nt = 0; nt < 8; nt++)
                #pragma unroll
                for (int j = 0; j < 4; j++) s[mt][nt][j] *= SC;

        if (jb * 64 + 63 > qb * 128 + mrow) {
            #pragma unroll
            for (int mt = 0; mt < 2; mt++) {
                int r0 = qb * 128 + mrow + mt * 16 + l4;
                int r1 = r0 + 8;
                #pragma unroll
                for (int nt = 0; nt < 8; nt++) {
                    int cn = jb * 64 + nt * 8 + lq * 2;
                    if (cn     > r0) s[mt][nt][0] = -1e30f;
                    if (cn + 1 > r0) s[mt][nt][1] = -1e30f;
                    if (cn     > r1) s[mt][nt][2] = -1e30f;
                    if (cn + 1 > r1) s[mt][nt][3] = -1e30f;
                }
            }
        }

        // online softmax per m-tile
        #pragma unroll
        for (int mt = 0; mt < 2; mt++) {
            float rm0 = -1e30f, rm1 = -1e30f;
            #pragma unroll
            for (int nt = 0; nt < 8; nt++) {
                rm0 = fmaxf(rm0, fmaxf(s[mt][nt][0], s[mt][nt][1]));
                rm1 = fmaxf(rm1, fmaxf(s[mt][nt][2], s[mt][nt][3]));
            }
            rm0 = fmaxf(rm0, __shfl_xor_sync(0xffffffffu, rm0, 1));
            rm0 = fmaxf(rm0, __shfl_xor_sync(0xffffffffu, rm0, 2));
            rm1 = fmaxf(rm1, __shfl_xor_sync(0xffffffffu, rm1, 1));
            rm1 = fmaxf(rm1, __shfl_xor_sync(0xffffffffu, rm1, 2));
            float nm0 = fmaxf(mx[mt][0], rm0), nm1 = fmaxf(mx[mt][1], rm1);
            float al0 = ex2(mx[mt][0] - nm0), al1 = ex2(mx[mt][1] - nm1);
            float rs0 = 0.f, rs1 = 0.f;
            #pragma unroll
            for (int nt = 0; nt < 8; nt++) {
                s[mt][nt][0] = ex2(s[mt][nt][0] - nm0); rs0 += s[mt][nt][0];
                s[mt][nt][1] = ex2(s[mt][nt][1] - nm0); rs0 += s[mt][nt][1];
                s[mt][nt][2] = ex2(s[mt][nt][2] - nm1); rs1 += s[mt][nt][2];
                s[mt][nt][3] = ex2(s[mt][nt][3] - nm1); rs1 += s[mt][nt][3];
            }
            rs0 += __shfl_xor_sync(0xffffffffu, rs0, 1);
            rs0 += __shfl_xor_sync(0xffffffffu, rs0, 2);
            rs1 += __shfl_xor_sync(0xffffffffu, rs1, 1);
            rs1 += __shfl_xor_sync(0xffffffffu, rs1, 2);
            ls[mt][0] = ls[mt][0] * al0 + rs0; mx[mt][0] = nm0;
            ls[mt][1] = ls[mt][1] * al1 + rs1; mx[mt][1] = nm1;
            #pragma unroll
            for (int nt = 0; nt < 8; nt++) {
                o[mt][nt][0] *= al0; o[mt][nt][1] *= al0;
                o[mt][nt][2] *= al1; o[mt][nt][3] *= al1;
            }
        }

        // O += P @ V : V ldmatrix shared across both m-tiles
        #pragma unroll
        for (int kp = 0; kp < 4; kp++) {
            uint32_t ap[2][4];
            #pragma unroll
            for (int mt = 0; mt < 2; mt++) {
                ap[mt][0] = packh2(s[mt][2 * kp][0],     s[mt][2 * kp][1]);
                ap[mt][1] = packh2(s[mt][2 * kp][2],     s[mt][2 * kp][3]);
                ap[mt][2] = packh2(s[mt][2 * kp + 1][0], s[mt][2 * kp + 1][1]);
                ap[mt][3] = packh2(s[mt][2 * kp + 1][2], s[mt][2 * kp + 1][3]);
            }
            uint32_t kaddr = vbase + kp * 16 * (KVP * 2);
            #pragma unroll
            for (int g = 0; g < 4; g++) {
                uint32_t b0, b1, b2, b3;
                ldsm4t(b0, b1, b2, b3, kaddr + g * 32);
                uint32_t bl[2] = {b0, b1}, bh2[2] = {b2, b3};
                #pragma unroll
                for (int mt = 0; mt < 2; mt++) {
                    mma_f16(o[mt][2 * g],     ap[mt], bl);
                    mma_f16(o[mt][2 * g + 1], ap[mt], bh2);
                }
            }
        }
        __syncthreads();
    }

    // Epilogue: write y (fp16) in [B,C,E], e = h*64 + d
    int h_ = bh & 15, b_ = bh >> 4;
    #pragma unroll
    for (int mt = 0; mt < 2; mt++) {
        int r0g = qb * 128 + mrow + mt * 16 + l4;
        float il0 = 1.0f / ls[mt][0], il1 = 1.0f / ls[mt][1];
        #pragma unroll
        for (int nt = 0; nt < 8; nt++) {
            int d = nt * 8 + lq * 2;
            size_t base = ((size_t)b_ * PC + r0g) * PE + h_ * PHD + d;
            *(uint32_t*)&g_yh[base] =
                packh2(o[mt][nt][0] * il0, o[mt][nt][1] * il0);
            *(uint32_t*)&g_yh[base + (size_t)8 * PE] =
                packh2(o[mt][nt][2] * il1, o[mt][nt][3] * il1);
        }
    }
}

// ---------------------------------------------------------------------------
extern "C" void kernel_launch(void* const* d_in, const int* in_sizes, int n_in,
                              void* d_out, int out_size)
{
    const float* x  = (const float*)d_in[0];
    const float* Wa = (const float*)d_in[1];
    const float* Wp = (const float*)d_in[2];
    float* out = (float*)d_out;

    size_t smemG = (size_t)4 * GSZ * sizeof(__half);     // 73728
    size_t smemA = (size_t)4 * KV_SZ * sizeof(__half);   // 36864

    cudaFuncSetAttribute(gemm_h<PN3, 0>,
                         cudaFuncAttributeMaxDynamicSharedMemorySize, (int)smemG);
    cudaFuncSetAttribute(gemm_h<PE, 1>,
                         cudaFuncAttributeMaxDynamicSharedMemorySize, (int)smemG);
    cudaFuncSetAttribute(attn_h,
                         cudaFuncAttributeMaxDynamicSharedMemorySize, (int)smemA);

    // Pre-pass: x -> fp16; W_attn, W_proj -> transposed fp16
    uint2* d_xh;    cudaGetSymbolAddress((void**)&d_xh,  g_xh);
    __half* d_watT; cudaGetSymbolAddress((void**)&d_watT, g_watT);
    __half* d_wptT; cudaGetSymbolAddress((void**)&d_wptT, g_wptT);
    {
        int n4 = PM * PK / 4;
        cvt_h4<<<(n4 + 255) / 256, 256>>>((const float4*)x, d_xh, n4);
        transpose_h<<<dim3(PN3 / 32, PK / 32), dim3(32, 8)>>>(Wa, d_watT, PK, PN3);
        transpose_h<<<dim3(PE / 32, PK / 32), dim3(32, 8)>>>(Wp, d_wptT, PK, PE);
    }

    gemm_h<PN3, 0><<<dim3(PN3 / 128, PM / 128), 128, smemG>>>(nullptr);
    attn_h<<<dim3(PC / 128, PB * PH), 128, smemA>>>();
    gemm_h<PE, 1><<<dim3(PE / 128, PM / 128), 128, smemG>>>(out);
}

// round 8
// speedup vs baseline: 2.1781x; 1.0462x over previous
#include <cuda_runtime.h>
#include <cuda_fp16.h>
#include <cstdint>

#define PB 4
#define PC 2048
#define PE 1024
#define PH 16
#define PHD 64
#define PM (PB*PC)        // 8192
#define PK PE             // 1024
#define PN3 (3*PE)        // 3072

// fp16 scratch (device globals: allocation-free rule)
__device__ __half g_xh  [(size_t)PM*PK];
__device__ __half g_watT[(size_t)PN3*PK];   // W_attn^T [3072][1024]
__device__ __half g_wptT[(size_t)PE*PK];    // W_proj^T [1024][1024]
__device__ __half g_qh  [(size_t)PB*PH*PC*PHD];
__device__ __half g_kh  [(size_t)PB*PH*PC*PHD];
__device__ __half g_vh  [(size_t)PB*PH*PC*PHD];
__device__ __half g_yh  [(size_t)PM*PE];

// ---------------------------------------------------------------------------
// Helpers
// ---------------------------------------------------------------------------
__device__ __forceinline__ float ex2(float x) {
    float r;
    asm("ex2.approx.f32 %0, %1;" : "=f"(r) : "f"(x));
    return r;
}
__device__ __forceinline__ uint32_t packh2(float lo, float hi) {
    __half2 p = __floats2half2_rn(lo, hi);
    return *(uint32_t*)&p;
}
__device__ __forceinline__ void mma_f16(float* c, const uint32_t* a, const uint32_t* b) {
    asm volatile(
        "mma.sync.aligned.m16n8k16.row.col.f32.f16.f16.f32 "
        "{%0,%1,%2,%3}, {%4,%5,%6,%7}, {%8,%9}, {%0,%1,%2,%3};"
        : "+f"(c[0]), "+f"(c[1]), "+f"(c[2]), "+f"(c[3])
        : "r"(a[0]), "r"(a[1]), "r"(a[2]), "r"(a[3]), "r"(b[0]), "r"(b[1]));
}
__device__ __forceinline__ void ldsm4t(uint32_t& r0, uint32_t& r1,
                                       uint32_t& r2, uint32_t& r3, uint32_t addr) {
    asm volatile("ldmatrix.sync.aligned.m8n8.x4.trans.shared.b16 {%0,%1,%2,%3}, [%4];"
                 : "=r"(r0), "=r"(r1), "=r"(r2), "=r"(r3) : "r"(addr));
}
__device__ __forceinline__ void cp16(void* smem_dst, const void* gsrc) {
    uint32_t d = (uint32_t)__cvta_generic_to_shared(smem_dst);
    asm volatile("cp.async.cg.shared.global [%0], [%1], 16;" :: "r"(d), "l"(gsrc));
}
__device__ __forceinline__ void cp_commit() { asm volatile("cp.async.commit_group;"); }
template<int N> __device__ __forceinline__ void cp_wait() {
    asm volatile("cp.async.wait_group %0;" :: "n"(N));
}

// ---------------------------------------------------------------------------
// Pre-pass: fp32 -> fp16
// ---------------------------------------------------------------------------
__global__ void cvt_h4(const float4* __restrict__ src, uint2* __restrict__ dst, int n4)
{
    int i = blockIdx.x * blockDim.x + threadIdx.x;
    if (i < n4) {
        float4 v = src[i];
        dst[i] = make_uint2(packh2(v.x, v.y), packh2(v.z, v.w));
    }
}

// src [Ksrc][Nsrc] fp32 -> dst [Nsrc][Ksrc] fp16
__global__ void transpose_h(const float* __restrict__ src, __half* __restrict__ dst,
                            int Ksrc, int Nsrc)
{
    __shared__ __half t[32][33];
    int bx = blockIdx.x, by = blockIdx.y;
    int tx = threadIdx.x, ty = threadIdx.y;    // (32, 8)
    #pragma unroll
    for (int j = 0; j < 4; j++) {
        int y = by * 32 + ty + j * 8;
        t[ty + j * 8][tx] = __float2half_rn(src[(size_t)y * Nsrc + bx * 32 + tx]);
    }
    __syncthreads();
    #pragma unroll
    for (int j = 0; j < 4; j++) {
        int n = bx * 32 + ty + j * 8;
        dst[(size_t)n * Ksrc + by * 32 + tx] = t[tx][ty + j * 8];
    }
}

// ---------------------------------------------------------------------------
// FP16 GEMM: CTA 128x128, BK=64, 4 warps, warp tile 64x64.
// 3-stage cp.async pipeline, ONE __syncthreads per iteration.
// EPI 0: A=g_xh, B=g_watT -> scatter fp16 q/k/v head-major
// EPI 1: A=g_yh, B=g_wptT -> fp32 out
// ---------------------------------------------------------------------------
#define GP 72
#define GOP (128*GP)          // halves per operand per stage (9216)
#define GSTAGE (2*GOP)        // A + B per stage (18432 halves = 36864 B)

template<int N, int EPI>
__global__ __launch_bounds__(128, 2)
void gemm_h(float* __restrict__ Cout)
{
    extern __shared__ __half sh[];   // 3 * GSTAGE halves

    const __half* Ap = EPI ? g_yh   : g_xh;
    const __half* Bp = EPI ? g_wptT : g_watT;
    const int K = PK;

    const int tid = threadIdx.x;
    const int warp = tid >> 5, lane = tid & 31;
    const int l4 = lane >> 2, lq = lane & 3;
    const int wm = (warp >> 1) * 64, wn = (warp & 1) * 64;
    const int bx = blockIdx.x, by = blockIdx.y;

    float acc[4][8][4];
    #pragma unroll
    for (int i = 0; i < 4; i++)
        #pragma unroll
        for (int j = 0; j < 8; j++)
            #pragma unroll
            for (int r = 0; r < 4; r++) acc[i][j][r] = 0.f;

    auto issue = [&](int it) {
        __half* Sb = sh + (it % 3) * GSTAGE;
        int k0 = it * 64;
        #pragma unroll
        for (int i = 0; i < 8; i++) {
            int idx = tid + i * 128;
            int r = idx >> 3, c = idx & 7;
            cp16(Sb + r * GP + c * 8, Ap + (size_t)(by * 128 + r) * K + k0 + c * 8);
        }
        #pragma unroll
        for (int i = 0; i < 8; i++) {
            int idx = tid + i * 128;
            int r = idx >> 3, c = idx & 7;
            cp16(Sb + GOP + r * GP + c * 8, Bp + (size_t)(bx * 128 + r) * K + k0 + c * 8);
        }
        cp_commit();
    };

    issue(0); issue(1);
    const int NIT = K / 64;
    #pragma unroll 1
    for (int it = 0; it < NIT; ++it) {
        if (it < NIT - 1) cp_wait<1>(); else cp_wait<0>();
        __syncthreads();            // single barrier per iter (3-stage slack)
        const __half* Ab = sh + (it % 3) * GSTAGE;
        const __half* Bb = Ab + GOP;

        #pragma unroll
        for (int ks = 0; ks < 4; ks++) {
            int k = ks * 16;
            uint32_t a[4][4], b[8][2];
            #pragma unroll
            for (int mt = 0; mt < 4; mt++) {
                int m = wm + mt * 16 + l4;
                a[mt][0] = *(const uint32_t*)&Ab[m * GP + k + 2 * lq];
                a[mt][1] = *(const uint32_t*)&Ab[(m + 8) * GP + k + 2 * lq];
                a[mt][2] = *(const uint32_t*)&Ab[m * GP + k + 8 + 2 * lq];
                a[mt][3] = *(const uint32_t*)&Ab[(m + 8) * GP + k + 8 + 2 * lq];
            }
            #pragma unroll
            for (int nt = 0; nt < 8; nt++) {
                int n = wn + nt * 8 + l4;
                b[nt][0] = *(const uint32_t*)&Bb[n * GP + k + 2 * lq];
                b[nt][1] = *(const uint32_t*)&Bb[n * GP + k + 8 + 2 * lq];
            }
            #pragma unroll
            for (int mt = 0; mt < 4; mt++)
                #pragma unroll
                for (int nt = 0; nt < 8; nt++)
                    mma_f16(acc[mt][nt], a[mt], b[nt]);
        }
        if (it + 2 < NIT) issue(it + 2);
    }

    // Epilogue
    #pragma unroll
    for (int mt = 0; mt < 4; mt++) {
        #pragma unroll
        for (int nt = 0; nt < 8; nt++) {
            int gm = by * 128 + wm + mt * 16 + l4;
            int gn = bx * 128 + wn + nt * 8 + lq * 2;
            if (EPI == 0) {
                int which = gn >> 10;
                int hn = gn & 1023;
                int h = hn >> 6, d = hn & 63;
                __half* dst = (which == 0) ? g_qh : (which == 1 ? g_kh : g_vh);
                int b_ = gm >> 11, c_ = gm & 2047;
                size_t base = (((size_t)(b_ * PH + h)) * PC + c_) * PHD + d;
                *(uint32_t*)&dst[base] = packh2(acc[mt][nt][0], acc[mt][nt][1]);
                *(uint32_t*)&dst[base + (size_t)8 * PHD] =
                    packh2(acc[mt][nt][2], acc[mt][nt][3]);
            } else {
                *(float2*)&Cout[(size_t)gm * N + gn] =
                    make_float2(acc[mt][nt][0], acc[mt][nt][1]);
                *(float2*)&Cout[(size_t)(gm + 8) * N + gn] =
                    make_float2(acc[mt][nt][2], acc[mt][nt][3]);
            }
        }
    }
}

// ---------------------------------------------------------------------------
// FP16 flash attention: CTA = 128 q-rows, 4 warps x 32 rows (2 m-tiles each).
// 3-stage KV pipeline, one barrier per kv-block. Persistent Q frags.
// ---------------------------------------------------------------------------
#define KVP 72
#define KVOP (64*KVP)         // halves per operand per stage (4608)
#define KVSTAGE (2*KVOP)      // K + V per stage (9216 halves = 18432 B)

__global__ __launch_bounds__(128, 2)
void attn_h()
{
    extern __shared__ __half sh[];   // 3 * KVSTAGE halves

    const int qb = (int)gridDim.x - 1 - (int)blockIdx.x;   // big work first
    const int bh = blockIdx.y;
    const __half* Qg = g_qh + (size_t)bh * PC * PHD + (size_t)qb * 128 * PHD;
    const __half* Kg = g_kh + (size_t)bh * PC * PHD;
    const __half* Vg = g_vh + (size_t)bh * PC * PHD;

    const int tid = threadIdx.x;
    const int warp = tid >> 5, lane = tid & 31;
    const int l4 = lane >> 2, lq = lane & 3;
    const int mrow = warp * 32;

    // Persistent Q fragments
    uint32_t aq[2][4][4];
    #pragma unroll
    for (int mt = 0; mt < 2; mt++) {
        const int r0 = mrow + mt * 16 + l4, r1 = r0 + 8;
        #pragma unroll
        for (int kt = 0; kt < 4; kt++) {
            int k = kt * 16;
            aq[mt][kt][0] = *(const uint32_t*)&Qg[r0 * PHD + k + 2 * lq];
            aq[mt][kt][1] = *(const uint32_t*)&Qg[r1 * PHD + k + 2 * lq];
            aq[mt][kt][2] = *(const uint32_t*)&Qg[r0 * PHD + k + 8 + 2 * lq];
            aq[mt][kt][3] = *(const uint32_t*)&Qg[r1 * PHD + k + 8 + 2 * lq];
        }
    }

    auto issueKV = [&](int jb) {
        __half* Sb = sh + (jb % 3) * KVSTAGE;
        const __half* kg = Kg + (size_t)jb * 64 * PHD;
        const __half* vg = Vg + (size_t)jb * 64 * PHD;
        #pragma unroll
        for (int i = 0; i < 4; i++) {
            int idx = tid + i * 128;
            int r = idx >> 3, c = idx & 7;
            cp16(Sb + r * KVP + c * 8, kg + r * PHD + c * 8);
            cp16(Sb + KVOP + r * KVP + c * 8, vg + r * PHD + c * 8);
        }
        cp_commit();
    };

    float o[2][8][4];
    #pragma unroll
    for (int mt = 0; mt < 2; mt++)
        #pragma unroll
        for (int nt = 0; nt < 8; nt++)
            #pragma unroll
            for (int j = 0; j < 4; j++) o[mt][nt][j] = 0.f;
    float mx[2][2], ls[2][2];
    #pragma unroll
    for (int mt = 0; mt < 2; mt++) {
        mx[mt][0] = -1e30f; mx[mt][1] = -1e30f;
        ls[mt][0] = 0.f;    ls[mt][1] = 0.f;
    }

    const float SC = 0.125f * 1.4426950408889634f;   // 1/sqrt(64) * log2(e)
    const int NJB = 2 * qb + 2;
    const int vlane = (lane & 15) * (KVP * 2) + (lane & 16);

    issueKV(0);
    if (NJB > 1) issueKV(1);

    #pragma unroll 1
    for (int jb = 0; jb < NJB; ++jb) {
        if (jb < NJB - 1) cp_wait<1>(); else cp_wait<0>();
        __syncthreads();            // single barrier per kv-block
        const __half* Kb = sh + (jb % 3) * KVSTAGE;
        const __half* Vb = Kb + KVOP;
        uint32_t vbase = (uint32_t)__cvta_generic_to_shared(Vb) + vlane;

        // S = Q K^T
        float s[2][8][4];
        #pragma unroll
        for (int mt = 0; mt < 2; mt++)
            #pragma unroll
            for (int nt = 0; nt < 8; nt++)
                #pragma unroll
                for (int j = 0; j < 4; j++) s[mt][nt][j] = 0.f;

        #pragma unroll
        for (int kt = 0; kt < 4; kt++) {
            int k = kt * 16;
            #pragma unroll
            for (int nt = 0; nt < 8; nt++) {
                uint32_t b[2];
                b[0] = *(const uint32_t*)&Kb[(nt * 8 + l4) * KVP + k + 2 * lq];
                b[1] = *(const uint32_t*)&Kb[(nt * 8 + l4) * KVP + k + 8 + 2 * lq];
                mma_f16(s[0][nt], aq[0][kt], b);
                mma_f16(s[1][nt], aq[1][kt], b);
            }
        }

        // scale (log2 domain) + causal mask
        #pragma unroll
        for (int mt = 0; mt < 2; mt++)
            #pragma unroll
            for (int nt = 0; nt < 8; nt++)
                #pragma unroll
                for (int j = 0; j < 4; j++) s[mt][nt][j] *= SC;

        if (jb * 64 + 63 > qb * 128 + mrow) {
            #pragma unroll
            for (int mt = 0; mt < 2; mt++) {
                int r0 = qb * 128 + mrow + mt * 16 + l4;
                int r1 = r0 + 8;
                #pragma unroll
                for (int nt = 0; nt < 8; nt++) {
                    int cn = jb * 64 + nt * 8 + lq * 2;
                    if (cn     > r0) s[mt][nt][0] = -1e30f;
                    if (cn + 1 > r0) s[mt][nt][1] = -1e30f;
                    if (cn     > r1) s[mt][nt][2] = -1e30f;
                    if (cn + 1 > r1) s[mt][nt][3] = -1e30f;
                }
            }
        }

        // online softmax per m-tile
        #pragma unroll
        for (int mt = 0; mt < 2; mt++) {
            float rm0 = -1e30f, rm1 = -1e30f;
            #pragma unroll
            for (int nt = 0; nt < 8; nt++) {
                rm0 = fmaxf(rm0, fmaxf(s[mt][nt][0], s[mt][nt][1]));
                rm1 = fmaxf(rm1, fmaxf(s[mt][nt][2], s[mt][nt][3]));
            }
            rm0 = fmaxf(rm0, __shfl_xor_sync(0xffffffffu, rm0, 1));
            rm0 = fmaxf(rm0, __shfl_xor_sync(0xffffffffu, rm0, 2));
            rm1 = fmaxf(rm1, __shfl_xor_sync(0xffffffffu, rm1, 1));
            rm1 = fmaxf(rm1, __shfl_xor_sync(0xffffffffu, rm1, 2));
            float nm0 = fmaxf(mx[mt][0], rm0), nm1 = fmaxf(mx[mt][1], rm1);
            float al0 = ex2(mx[mt][0] - nm0), al1 = ex2(mx[mt][1] - nm1);
            float rs0 = 0.f, rs1 = 0.f;
            #pragma unroll
            for (int nt = 0; nt < 8; nt++) {
                s[mt][nt][0] = ex2(s[mt][nt][0] - nm0); rs0 += s[mt][nt][0];
                s[mt][nt][1] = ex2(s[mt][nt][1] - nm0); rs0 += s[mt][nt][1];
                s[mt][nt][2] = ex2(s[mt][nt][2] - nm1); rs1 += s[mt][nt][2];
                s[mt][nt][3] = ex2(s[mt][nt][3] - nm1); rs1 += s[mt][nt][3];
            }
            rs0 += __shfl_xor_sync(0xffffffffu, rs0, 1);
            rs0 += __shfl_xor_sync(0xffffffffu, rs0, 2);
            rs1 += __shfl_xor_sync(0xffffffffu, rs1, 1);
            rs1 += __shfl_xor_sync(0xffffffffu, rs1, 2);
            ls[mt][0] = ls[mt][0] * al0 + rs0; mx[mt][0] = nm0;
            ls[mt][1] = ls[mt][1] * al1 + rs1; mx[mt][1] = nm1;
            #pragma unroll
            for (int nt = 0; nt < 8; nt++) {
                o[mt][nt][0] *= al0; o[mt][nt][1] *= al0;
                o[mt][nt][2] *= al1; o[mt][nt][3] *= al1;
            }
        }

        // O += P @ V : V ldmatrix shared across both m-tiles
        #pragma unroll
        for (int kp = 0; kp < 4; kp++) {
            uint32_t ap[2][4];
            #pragma unroll
            for (int mt = 0; mt < 2; mt++) {
                ap[mt][0] = packh2(s[mt][2 * kp][0],     s[mt][2 * kp][1]);
                ap[mt][1] = packh2(s[mt][2 * kp][2],     s[mt][2 * kp][3]);
                ap[mt][2] = packh2(s[mt][2 * kp + 1][0], s[mt][2 * kp + 1][1]);
                ap[mt][3] = packh2(s[mt][2 * kp + 1][2], s[mt][2 * kp + 1][3]);
            }
            uint32_t kaddr = vbase + kp * 16 * (KVP * 2);
            #pragma unroll
            for (int g = 0; g < 4; g++) {
                uint32_t b0, b1, b2, b3;
                ldsm4t(b0, b1, b2, b3, kaddr + g * 32);
                uint32_t bl[2] = {b0, b1}, bh2[2] = {b2, b3};
                #pragma unroll
                for (int mt = 0; mt < 2; mt++) {
                    mma_f16(o[mt][2 * g],     ap[mt], bl);
                    mma_f16(o[mt][2 * g + 1], ap[mt], bh2);
                }
            }
        }
        if (jb + 2 < NJB) issueKV(jb + 2);
    }

    // Epilogue: write y (fp16) in [B,C,E], e = h*64 + d
    int h_ = bh & 15, b_ = bh >> 4;
    #pragma unroll
    for (int mt = 0; mt < 2; mt++) {
        int r0g = qb * 128 + mrow + mt * 16 + l4;
        float il0 = 1.0f / ls[mt][0], il1 = 1.0f / ls[mt][1];
        #pragma unroll
        for (int nt = 0; nt < 8; nt++) {
            int d = nt * 8 + lq * 2;
            size_t base = ((size_t)b_ * PC + r0g) * PE + h_ * PHD + d;
            *(uint32_t*)&g_yh[base] =
                packh2(o[mt][nt][0] * il0, o[mt][nt][1] * il0);
            *(uint32_t*)&g_yh[base + (size_t)8 * PE] =
                packh2(o[mt][nt][2] * il1, o[mt][nt][3] * il1);
        }
    }
}

// ---------------------------------------------------------------------------
extern "C" void kernel_launch(void* const* d_in, const int* in_sizes, int n_in,
                              void* d_out, int out_size)
{
    const float* x  = (const float*)d_in[0];
    const float* Wa = (const float*)d_in[1];
    const float* Wp = (const float*)d_in[2];
    float* out = (float*)d_out;

    size_t smemG = (size_t)3 * GSTAGE * sizeof(__half);     // 110592
    size_t smemA = (size_t)3 * KVSTAGE * sizeof(__half);    // 55296

    cudaFuncSetAttribute(gemm_h<PN3, 0>,
                         cudaFuncAttributeMaxDynamicSharedMemorySize, (int)smemG);
    cudaFuncSetAttribute(gemm_h<PE, 1>,
                         cudaFuncAttributeMaxDynamicSharedMemorySize, (int)smemG);
    cudaFuncSetAttribute(attn_h,
                         cudaFuncAttributeMaxDynamicSharedMemorySize, (int)smemA);

    // Pre-pass: x -> fp16; W_attn, W_proj -> transposed fp16
    uint2* d_xh;    cudaGetSymbolAddress((void**)&d_xh,  g_xh);
    __half* d_watT; cudaGetSymbolAddress((void**)&d_watT, g_watT);
    __half* d_wptT; cudaGetSymbolAddress((void**)&d_wptT, g_wptT);
    {
        int n4 = PM * PK / 4;
        cvt_h4<<<(n4 + 255) / 256, 256>>>((const float4*)x, d_xh, n4);
        transpose_h<<<dim3(PN3 / 32, PK / 32), dim3(32, 8)>>>(Wa, d_watT, PK, PN3);
        transpose_h<<<dim3(PE / 32, PK / 32), dim3(32, 8)>>>(Wp, d_wptT, PK, PE);
    }

    gemm_h<PN3, 0><<<dim3(PN3 / 128, PM / 128), 128, smemG>>>(nullptr);
    attn_h<<<dim3(PC / 128, PB * PH), 128, smemA>>>();
    gemm_h<PE, 1><<<dim3(PE / 128, PM / 128), 128, smemG>>>(out);
}